// round 2
// baseline (speedup 1.0000x reference)
#include <cuda_runtime.h>

// Problem constants
#define D_MODEL 512
#define S_LEN   2048
#define NB      2
#define NH      8
#define DK      64
#define MROWS   (NB * S_LEN)    // 4096
#define BHCNT   (NB * NH)       // 16

// Scratch (static device globals: allocation-free, graph-capturable)
__device__ float g_Q[BHCNT * S_LEN * DK];   // head-split, pre-scaled by 1/8
__device__ float g_K[BHCNT * S_LEN * DK];
__device__ float g_V[BHCNT * S_LEN * DK];
__device__ float g_O[MROWS * D_MODEL];      // merged-head attention output

// ---------------------------------------------------------------------------
// Fused Q/K/V projection GEMM: out = x @ W^T + b, written head-split.
// 128x128x16 tile, 256 threads, 8x8 micro-tile per thread.
// blockIdx.z: 0 -> Q (scaled by 0.125), 1 -> K, 2 -> V
// ---------------------------------------------------------------------------
__global__ __launch_bounds__(256, 2) void proj_kernel(
    const float* __restrict__ qin, const float* __restrict__ vin,
    const float* __restrict__ kin,
    const float* __restrict__ w_q, const float* __restrict__ b_q,
    const float* __restrict__ w_k, const float* __restrict__ b_k,
    const float* __restrict__ w_v, const float* __restrict__ b_v)
{
    __shared__ float As[16][132];
    __shared__ float Bs[16][132];

    const float* x; const float* W; const float* bias; float* dst; float scale;
    const int z = blockIdx.z;
    if (z == 0)      { x = qin; W = w_q; bias = b_q; dst = g_Q; scale = 0.125f; }
    else if (z == 1) { x = kin; W = w_k; bias = b_k; dst = g_K; scale = 1.0f; }
    else             { x = vin; W = w_v; bias = b_v; dst = g_V; scale = 1.0f; }

    const int tx = threadIdx.x, ty = threadIdx.y;
    const int tid = ty * 16 + tx;
    const int m0 = blockIdx.y * 128, n0 = blockIdx.x * 128;
    const int lr = tid >> 2;          // 0..63
    const int lk = (tid & 3) << 2;    // 0,4,8,12

    float acc[8][8];
#pragma unroll
    for (int i = 0; i < 8; i++)
#pragma unroll
        for (int j = 0; j < 8; j++) acc[i][j] = 0.0f;

    for (int k0 = 0; k0 < D_MODEL; k0 += 16) {
        __syncthreads();
        float4 a0 = *(const float4*)&x[(m0 + lr) * D_MODEL + k0 + lk];
        float4 a1 = *(const float4*)&x[(m0 + lr + 64) * D_MODEL + k0 + lk];
        float4 b0 = *(const float4*)&W[(n0 + lr) * D_MODEL + k0 + lk];
        float4 b1 = *(const float4*)&W[(n0 + lr + 64) * D_MODEL + k0 + lk];
        As[lk + 0][lr] = a0.x; As[lk + 1][lr] = a0.y; As[lk + 2][lr] = a0.z; As[lk + 3][lr] = a0.w;
        As[lk + 0][lr + 64] = a1.x; As[lk + 1][lr + 64] = a1.y; As[lk + 2][lr + 64] = a1.z; As[lk + 3][lr + 64] = a1.w;
        Bs[lk + 0][lr] = b0.x; Bs[lk + 1][lr] = b0.y; Bs[lk + 2][lr] = b0.z; Bs[lk + 3][lr] = b0.w;
        Bs[lk + 0][lr + 64] = b1.x; Bs[lk + 1][lr + 64] = b1.y; Bs[lk + 2][lr + 64] = b1.z; Bs[lk + 3][lr + 64] = b1.w;
        __syncthreads();
#pragma unroll
        for (int kk = 0; kk < 16; kk++) {
            float a[8], b[8];
            *(float4*)&a[0] = *(const float4*)&As[kk][ty * 8];
            *(float4*)&a[4] = *(const float4*)&As[kk][ty * 8 + 4];
            *(float4*)&b[0] = *(const float4*)&Bs[kk][tx * 8];
            *(float4*)&b[4] = *(const float4*)&Bs[kk][tx * 8 + 4];
#pragma unroll
            for (int i = 0; i < 8; i++)
#pragma unroll
                for (int j = 0; j < 8; j++)
                    acc[i][j] = fmaf(a[i], b[j], acc[i][j]);
        }
    }

#pragma unroll
    for (int i = 0; i < 8; i++) {
        const int mm = m0 + ty * 8 + i;
        const int bb = mm >> 11, ss = mm & (S_LEN - 1);
#pragma unroll
        for (int j = 0; j < 8; j++) {
            const int d = n0 + tx * 8 + j;
            const int h = d >> 6, dk = d & 63;
            dst[(((bb << 3) | h) * S_LEN + ss) * DK + dk] = (acc[i][j] + bias[d]) * scale;
        }
    }
}

// ---------------------------------------------------------------------------
// Flash attention: per (bh, q-tile of 128). BK=64. Online softmax.
// 256 threads (16x16); thread = 8 q-rows x 4 cols micro-tile.
// Smem: Qs[64][132] (d-major), Ks[64][68] (d-major), Vs[64][68], Ps[64][132]
// ---------------------------------------------------------------------------
__global__ __launch_bounds__(256, 2) void attn_kernel()
{
    extern __shared__ float smn[];
    float* Qs = smn;                      // 64*132 = 8448
    float* Ks = Qs + 64 * 132;            // 64*68  = 4352
    float* Vs = Ks + 64 * 68;             // 64*68  = 4352
    float* Ps = Vs + 64 * 68;             // 64*132 = 8448

    const int tx = threadIdx.x, ty = threadIdx.y;
    const int tid = ty * 16 + tx;
    const int bh = blockIdx.y;
    const int q0 = blockIdx.x * 128;

    const float* Qg = g_Q + (bh * S_LEN + q0) * DK;
    const float* Kg = g_K + bh * S_LEN * DK;
    const float* Vg = g_V + bh * S_LEN * DK;

    // Load + transpose Q tile: Qs[d][q]
    for (int idx = tid; idx < 128 * 64; idx += 256) {
        const int qq = idx >> 6, d = idx & 63;
        Qs[d * 132 + qq] = Qg[idx];
    }

    float m[8], l[8], o[8][4];
#pragma unroll
    for (int i = 0; i < 8; i++) {
        m[i] = -1e30f; l[i] = 0.0f;
#pragma unroll
        for (int j = 0; j < 4; j++) o[i][j] = 0.0f;
    }

    for (int kt = 0; kt < S_LEN / 64; kt++) {
        __syncthreads();   // previous iter done reading Ks/Vs/Ps; also fences Q load at kt=0
        const float* kg = Kg + kt * 64 * DK;
        const float* vg = Vg + kt * 64 * DK;
        for (int idx = tid; idx < 64 * 64; idx += 256) {
            const int r = idx >> 6, d = idx & 63;
            Ks[d * 68 + r] = kg[idx];
            Vs[r * 68 + d] = vg[idx];
        }
        __syncthreads();

        // S = Q K^T (scale already folded into Q)
        float s[8][4];
#pragma unroll
        for (int i = 0; i < 8; i++)
#pragma unroll
            for (int j = 0; j < 4; j++) s[i][j] = 0.0f;

#pragma unroll 8
        for (int d = 0; d < 64; d++) {
            float a[8], b[4];
            *(float4*)&a[0] = *(const float4*)&Qs[d * 132 + ty * 8];
            *(float4*)&a[4] = *(const float4*)&Qs[d * 132 + ty * 8 + 4];
            *(float4*)&b[0] = *(const float4*)&Ks[d * 68 + tx * 4];
#pragma unroll
            for (int i = 0; i < 8; i++)
#pragma unroll
                for (int j = 0; j < 4; j++)
                    s[i][j] = fmaf(a[i], b[j], s[i][j]);
        }

        // Online softmax (row reductions across the 16 tx lanes)
#pragma unroll
        for (int i = 0; i < 8; i++) {
            float mx = fmaxf(fmaxf(s[i][0], s[i][1]), fmaxf(s[i][2], s[i][3]));
#pragma unroll
            for (int off = 8; off; off >>= 1)
                mx = fmaxf(mx, __shfl_xor_sync(0xffffffffu, mx, off));
            const float nm = fmaxf(m[i], mx);
            const float alpha = __expf(m[i] - nm);
            m[i] = nm;
            float sum = 0.0f;
#pragma unroll
            for (int j = 0; j < 4; j++) {
                s[i][j] = __expf(s[i][j] - nm);
                sum += s[i][j];
            }
#pragma unroll
            for (int off = 8; off; off >>= 1)
                sum += __shfl_xor_sync(0xffffffffu, sum, off);
            l[i] = l[i] * alpha + sum;
#pragma unroll
            for (int j = 0; j < 4; j++) o[i][j] *= alpha;
        }

        // Stage P to smem: Ps[k][q]
#pragma unroll
        for (int j = 0; j < 4; j++)
#pragma unroll
            for (int i = 0; i < 8; i++)
                Ps[(tx * 4 + j) * 132 + ty * 8 + i] = s[i][j];
        __syncthreads();

        // O += P V
#pragma unroll 8
        for (int kk = 0; kk < 64; kk++) {
            float a[8], b[4];
            *(float4*)&a[0] = *(const float4*)&Ps[kk * 132 + ty * 8];
            *(float4*)&a[4] = *(const float4*)&Ps[kk * 132 + ty * 8 + 4];
            *(float4*)&b[0] = *(const float4*)&Vs[kk * 68 + tx * 4];
#pragma unroll
            for (int i = 0; i < 8; i++)
#pragma unroll
                for (int j = 0; j < 4; j++)
                    o[i][j] = fmaf(a[i], b[j], o[i][j]);
        }
    }

    // Normalize and write merged-head layout g_O[b*S + s][h*64 + c]
    const int b = bh >> 3, h = bh & 7;
#pragma unroll
    for (int i = 0; i < 8; i++) {
        const float inv = 1.0f / l[i];
        const int srow = q0 + ty * 8 + i;
        float4 r;
        r.x = o[i][0] * inv; r.y = o[i][1] * inv;
        r.z = o[i][2] * inv; r.w = o[i][3] * inv;
        *(float4*)&g_O[(b * S_LEN + srow) * D_MODEL + h * 64 + tx * 4] = r;
    }
}

// ---------------------------------------------------------------------------
// Output projection: d_out = g_O @ w_o^T + b_o   (plain [4096, 512] layout)
// ---------------------------------------------------------------------------
__global__ __launch_bounds__(256, 2) void outproj_kernel(
    const float* __restrict__ W, const float* __restrict__ bias,
    float* __restrict__ out)
{
    __shared__ float As[16][132];
    __shared__ float Bs[16][132];

    const float* x = g_O;
    const int tx = threadIdx.x, ty = threadIdx.y;
    const int tid = ty * 16 + tx;
    const int m0 = blockIdx.y * 128, n0 = blockIdx.x * 128;
    const int lr = tid >> 2;
    const int lk = (tid & 3) << 2;

    float acc[8][8];
#pragma unroll
    for (int i = 0; i < 8; i++)
#pragma unroll
        for (int j = 0; j < 8; j++) acc[i][j] = 0.0f;

    for (int k0 = 0; k0 < D_MODEL; k0 += 16) {
        __syncthreads();
        float4 a0 = *(const float4*)&x[(m0 + lr) * D_MODEL + k0 + lk];
        float4 a1 = *(const float4*)&x[(m0 + lr + 64) * D_MODEL + k0 + lk];
        float4 b0 = *(const float4*)&W[(n0 + lr) * D_MODEL + k0 + lk];
        float4 b1 = *(const float4*)&W[(n0 + lr + 64) * D_MODEL + k0 + lk];
        As[lk + 0][lr] = a0.x; As[lk + 1][lr] = a0.y; As[lk + 2][lr] = a0.z; As[lk + 3][lr] = a0.w;
        As[lk + 0][lr + 64] = a1.x; As[lk + 1][lr + 64] = a1.y; As[lk + 2][lr + 64] = a1.z; As[lk + 3][lr + 64] = a1.w;
        Bs[lk + 0][lr] = b0.x; Bs[lk + 1][lr] = b0.y; Bs[lk + 2][lr] = b0.z; Bs[lk + 3][lr] = b0.w;
        Bs[lk + 0][lr + 64] = b1.x; Bs[lk + 1][lr + 64] = b1.y; Bs[lk + 2][lr + 64] = b1.z; Bs[lk + 3][lr + 64] = b1.w;
        __syncthreads();
#pragma unroll
        for (int kk = 0; kk < 16; kk++) {
            float a[8], b[8];
            *(float4*)&a[0] = *(const float4*)&As[kk][ty * 8];
            *(float4*)&a[4] = *(const float4*)&As[kk][ty * 8 + 4];
            *(float4*)&b[0] = *(const float4*)&Bs[kk][tx * 8];
            *(float4*)&b[4] = *(const float4*)&Bs[kk][tx * 8 + 4];
#pragma unroll
            for (int i = 0; i < 8; i++)
#pragma unroll
                for (int j = 0; j < 8; j++)
                    acc[i][j] = fmaf(a[i], b[j], acc[i][j]);
        }
    }

#pragma unroll
    for (int i = 0; i < 8; i++) {
        const int mm = m0 + ty * 8 + i;
#pragma unroll
        for (int j = 0; j < 8; j++) {
            const int d = n0 + tx * 8 + j;
            out[mm * D_MODEL + d] = acc[i][j] + bias[d];
        }
    }
}

// ---------------------------------------------------------------------------
extern "C" void kernel_launch(void* const* d_in, const int* in_sizes, int n_in,
                              void* d_out, int out_size)
{
    // Input order (reference signature): q, v, k, w_q, b_q, w_k, b_k, w_v, b_v, w_o, b_o
    const float* q   = (const float*)d_in[0];
    const float* v   = (const float*)d_in[1];
    const float* k   = (const float*)d_in[2];
    const float* w_q = (const float*)d_in[3];
    const float* b_q = (const float*)d_in[4];
    const float* w_k = (const float*)d_in[5];
    const float* b_k = (const float*)d_in[6];
    const float* w_v = (const float*)d_in[7];
    const float* b_v = (const float*)d_in[8];
    const float* w_o = (const float*)d_in[9];
    const float* b_o = (const float*)d_in[10];
    float* out = (float*)d_out;

    const size_t attn_smem = 25600 * sizeof(float);  // 102400 B
    cudaFuncSetAttribute(attn_kernel, cudaFuncAttributeMaxDynamicSharedMemorySize,
                         (int)attn_smem);

    dim3 tpb(16, 16);
    // 1) Q/K/V projections (fused, z selects matrix)
    proj_kernel<<<dim3(D_MODEL / 128, MROWS / 128, 3), tpb>>>(
        q, v, k, w_q, b_q, w_k, b_k, w_v, b_v);
    // 2) Flash attention
    attn_kernel<<<dim3(S_LEN / 128, BHCNT), tpb, attn_smem>>>();
    // 3) Output projection
    outproj_kernel<<<dim3(D_MODEL / 128, MROWS / 128), tpb>>>(w_o, b_o, out);
}

// round 7
// speedup vs baseline: 1.9074x; 1.9074x over previous
#include <cuda_runtime.h>
#include <cstdint>

// Problem constants
#define D_MODEL 512
#define S_LEN   2048
#define NB      2
#define NH      8
#define DK      64
#define MROWS   (NB * S_LEN)    // 4096
#define BHCNT   (NB * NH)       // 16

// Scratch (static device globals: allocation-free, graph-capturable)
__device__ float g_Q[BHCNT * S_LEN * DK];   // head-split, pre-scaled by 1/8
__device__ float g_K[BHCNT * S_LEN * DK];
__device__ float g_V[BHCNT * S_LEN * DK];
__device__ float g_O[MROWS * D_MODEL];      // merged-head attention output

// ===========================================================================
// Helpers: legacy-path tf32 MMA (PTX ISA sm_80+, no 'a'-features) + cp.async
// ===========================================================================
__device__ __forceinline__ void mma_tf32(float* d, const uint32_t* a, const uint32_t* b)
{
    asm volatile(
        "mma.sync.aligned.m16n8k8.row.col.f32.tf32.tf32.f32 "
        "{%0,%1,%2,%3}, {%4,%5,%6,%7}, {%8,%9}, {%0,%1,%2,%3};"
        : "+f"(d[0]), "+f"(d[1]), "+f"(d[2]), "+f"(d[3])
        : "r"(a[0]), "r"(a[1]), "r"(a[2]), "r"(a[3]), "r"(b[0]), "r"(b[1]));
}

__device__ __forceinline__ uint32_t smem_u32(const void* p) {
    uint32_t addr;
    asm("{ .reg .u64 tmp; cvta.to.shared.u64 tmp, %1; cvt.u32.u64 %0, tmp; }"
        : "=r"(addr) : "l"(p));
    return addr;
}

__device__ __forceinline__ void cp_async16(uint32_t dst, const void* src) {
    asm volatile("cp.async.cg.shared.global [%0], [%1], 16;" :: "r"(dst), "l"(src));
}
__device__ __forceinline__ void cp_commit() {
    asm volatile("cp.async.commit_group;" ::: "memory");
}
template <int N>
__device__ __forceinline__ void cp_wait() {
    asm volatile("cp.async.wait_group %0;" :: "n"(N) : "memory");
}

// ===========================================================================
// tf32 mma.sync GEMM with 3xTF32 compensation: out = x @ W^T + bias
//   CTA tile 128x128, 8 warps (2x4), warp tile 64x32 (4x4 m16n8k8 tiles).
//   K chunks of 32, double-buffered cp.async. Raw fp32 in smem; hi/lo split
//   (hi = v & 0xFFFFE000 -> exact tf32; lo = v - hi) at fragment-load time.
//   mode 0: z selects Q/K/V projection, head-split output (Q scaled 0.125)
//   mode 1: x = g_O, W/bias from wq_/bq_ params, plain [4096,512] output
// Smem: 2 buffers x { A[128][36] | B[128][36] } floats = 73,728 B
// ===========================================================================
__global__ __launch_bounds__(256, 1) void tf32_gemm(
    const float* __restrict__ qx, const float* __restrict__ kx,
    const float* __restrict__ vx,
    const float* __restrict__ wq_, const float* __restrict__ bq_,
    const float* __restrict__ wk_, const float* __restrict__ bk_,
    const float* __restrict__ wv_, const float* __restrict__ bv_,
    float* __restrict__ outp, int mode)
{
    extern __shared__ __align__(16) float smf[];   // [buf][A/B][128][36]
    const uint32_t sb = smem_u32(smf);

    const float* x; const float* W; const float* bias; float* dst; float scale;
    if (mode == 0) {
        const int z = blockIdx.z;
        if (z == 0)      { x = qx; W = wq_; bias = bq_; dst = g_Q; scale = 0.125f; }
        else if (z == 1) { x = kx; W = wk_; bias = bk_; dst = g_K; scale = 1.0f; }
        else             { x = vx; W = wv_; bias = bv_; dst = g_V; scale = 1.0f; }
    } else {
        x = g_O; W = wq_; bias = bq_; dst = outp; scale = 1.0f;
    }

    const int tid = threadIdx.x;
    const int wid = tid >> 5, lid = tid & 31;
    const int g = lid >> 2, tg = lid & 3;
    const int mwarp = wid & 1, nwarp = wid >> 1;     // 2 x 4 warp grid
    const int m0 = blockIdx.y * 128, n0 = blockIdx.x * 128;

    // cp.async loader: 2048 x 16B per chunk (A: 1024, B: 1024), 8 per thread
    // smem float layout: buf*9216 + (isB?4608:0) + r*36 + c
    auto load_chunk = [&](int buf, int chunk) {
        const int k0 = chunk * 32;
#pragma unroll
        for (int t = 0; t < 8; t++) {
            const int f = tid + 256 * t;     // 0..2047
            const int isB = f >> 10;
            const int g2 = f & 1023;
            const int r = g2 >> 3, q = g2 & 7;
            const float* src = isB ? &W[(size_t)(n0 + r) * D_MODEL + k0 + q * 4]
                                   : &x[(size_t)(m0 + r) * D_MODEL + k0 + q * 4];
            const uint32_t doff = (uint32_t)(buf * 9216 + isB * 4608 + r * 36 + q * 4) * 4u;
            cp_async16(sb + doff, src);
        }
    };

    float acc[4][4][4];
#pragma unroll
    for (int i = 0; i < 4; i++)
#pragma unroll
        for (int j = 0; j < 4; j++)
#pragma unroll
            for (int e = 0; e < 4; e++) acc[i][j][e] = 0.0f;

    load_chunk(0, 0);
    cp_commit();

    for (int c = 0; c < 16; c++) {
        const int buf = c & 1;
        if (c < 15) {
            load_chunk(buf ^ 1, c + 1);
            cp_commit();
            cp_wait<1>();
        } else {
            cp_wait<0>();
        }
        __syncthreads();

        const float* Ab = smf + buf * 9216;
        const float* Bb = Ab + 4608;
#pragma unroll
        for (int ks = 0; ks < 32; ks += 8) {
            // ---- load + split A fragments (4 m-tiles x 4 regs) ----
            uint32_t ah[4][4], al[4][4];
#pragma unroll
            for (int i = 0; i < 4; i++) {
                const int r0 = mwarp * 64 + i * 16 + g;
                const float v0 = Ab[r0 * 36 + ks + tg];
                const float v1 = Ab[(r0 + 8) * 36 + ks + tg];
                const float v2 = Ab[r0 * 36 + ks + tg + 4];
                const float v3 = Ab[(r0 + 8) * 36 + ks + tg + 4];
                ah[i][0] = __float_as_uint(v0) & 0xFFFFE000u;
                ah[i][1] = __float_as_uint(v1) & 0xFFFFE000u;
                ah[i][2] = __float_as_uint(v2) & 0xFFFFE000u;
                ah[i][3] = __float_as_uint(v3) & 0xFFFFE000u;
                al[i][0] = __float_as_uint(v0 - __uint_as_float(ah[i][0]));
                al[i][1] = __float_as_uint(v1 - __uint_as_float(ah[i][1]));
                al[i][2] = __float_as_uint(v2 - __uint_as_float(ah[i][2]));
                al[i][3] = __float_as_uint(v3 - __uint_as_float(ah[i][3]));
            }
            // ---- load + split B fragments (4 n-tiles x 2 regs) ----
            uint32_t bh[4][2], bl[4][2];
#pragma unroll
            for (int j = 0; j < 4; j++) {
                const int rn = nwarp * 32 + j * 8 + g;
                const float v0 = Bb[rn * 36 + ks + tg];
                const float v1 = Bb[rn * 36 + ks + tg + 4];
                bh[j][0] = __float_as_uint(v0) & 0xFFFFE000u;
                bh[j][1] = __float_as_uint(v1) & 0xFFFFE000u;
                bl[j][0] = __float_as_uint(v0 - __uint_as_float(bh[j][0]));
                bl[j][1] = __float_as_uint(v1 - __uint_as_float(bh[j][1]));
            }
            // ---- 3xTF32: Ah*Bh + Al*Bh + Ah*Bl ----
#pragma unroll
            for (int i = 0; i < 4; i++)
#pragma unroll
                for (int j = 0; j < 4; j++) {
                    mma_tf32(acc[i][j], ah[i], bh[j]);
                    mma_tf32(acc[i][j], al[i], bh[j]);
                    mma_tf32(acc[i][j], ah[i], bl[j]);
                }
        }
        __syncthreads();
    }

    // ---- epilogue: bias + scale + store ----
#pragma unroll
    for (int j = 0; j < 4; j++) {
        const int n = n0 + nwarp * 32 + j * 8 + 2 * tg;
        const float bv0 = __ldg(&bias[n]), bv1 = __ldg(&bias[n + 1]);
#pragma unroll
        for (int i = 0; i < 4; i++) {
            const int mA = m0 + mwarp * 64 + i * 16 + g;
            const int mB = mA + 8;
            float2 r0, r1;
            r0.x = (acc[i][j][0] + bv0) * scale;
            r0.y = (acc[i][j][1] + bv1) * scale;
            r1.x = (acc[i][j][2] + bv0) * scale;
            r1.y = (acc[i][j][3] + bv1) * scale;
            if (mode == 0) {
                const int h = n >> 6, dk = n & 63;
                const int bA = mA >> 11, sA = mA & (S_LEN - 1);
                const int bB = mB >> 11, sB = mB & (S_LEN - 1);
                *(float2*)&dst[((size_t)(bA * NH + h) * S_LEN + sA) * DK + dk] = r0;
                *(float2*)&dst[((size_t)(bB * NH + h) * S_LEN + sB) * DK + dk] = r1;
            } else {
                *(float2*)&dst[(size_t)mA * D_MODEL + n] = r0;
                *(float2*)&dst[(size_t)mB * D_MODEL + n] = r1;
            }
        }
    }
}

// ---------------------------------------------------------------------------
// Flash attention (unchanged, verified): per (bh, q-tile of 128). BK=64.
// ---------------------------------------------------------------------------
__global__ __launch_bounds__(256, 2) void attn_kernel()
{
    extern __shared__ float smn[];
    float* Qs = smn;                      // 64*132 = 8448
    float* Ks = Qs + 64 * 132;            // 64*68  = 4352
    float* Vs = Ks + 64 * 68;             // 64*68  = 4352
    float* Ps = Vs + 64 * 68;             // 64*132 = 8448

    const int tx = threadIdx.x, ty = threadIdx.y;
    const int tid = ty * 16 + tx;
    const int bh = blockIdx.y;
    const int q0 = blockIdx.x * 128;

    const float* Qg = g_Q + (bh * S_LEN + q0) * DK;
    const float* Kg = g_K + bh * S_LEN * DK;
    const float* Vg = g_V + bh * S_LEN * DK;

    for (int idx = tid; idx < 128 * 64; idx += 256) {
        const int qq = idx >> 6, d = idx & 63;
        Qs[d * 132 + qq] = Qg[idx];
    }

    float m[8], l[8], o[8][4];
#pragma unroll
    for (int i = 0; i < 8; i++) {
        m[i] = -1e30f; l[i] = 0.0f;
#pragma unroll
        for (int j = 0; j < 4; j++) o[i][j] = 0.0f;
    }

    for (int kt = 0; kt < S_LEN / 64; kt++) {
        __syncthreads();
        const float* kg = Kg + kt * 64 * DK;
        const float* vg = Vg + kt * 64 * DK;
        for (int idx = tid; idx < 64 * 64; idx += 256) {
            const int r = idx >> 6, d = idx & 63;
            Ks[d * 68 + r] = kg[idx];
            Vs[r * 68 + d] = vg[idx];
        }
        __syncthreads();

        float s[8][4];
#pragma unroll
        for (int i = 0; i < 8; i++)
#pragma unroll
            for (int j = 0; j < 4; j++) s[i][j] = 0.0f;

#pragma unroll 8
        for (int d = 0; d < 64; d++) {
            float a[8], b[4];
            *(float4*)&a[0] = *(const float4*)&Qs[d * 132 + ty * 8];
            *(float4*)&a[4] = *(const float4*)&Qs[d * 132 + ty * 8 + 4];
            *(float4*)&b[0] = *(const float4*)&Ks[d * 68 + tx * 4];
#pragma unroll
            for (int i = 0; i < 8; i++)
#pragma unroll
                for (int j = 0; j < 4; j++)
                    s[i][j] = fmaf(a[i], b[j], s[i][j]);
        }

#pragma unroll
        for (int i = 0; i < 8; i++) {
            float mx = fmaxf(fmaxf(s[i][0], s[i][1]), fmaxf(s[i][2], s[i][3]));
#pragma unroll
            for (int off = 8; off; off >>= 1)
                mx = fmaxf(mx, __shfl_xor_sync(0xffffffffu, mx, off));
            const float nm = fmaxf(m[i], mx);
            const float alpha = __expf(m[i] - nm);
            m[i] = nm;
            float sum = 0.0f;
#pragma unroll
            for (int j = 0; j < 4; j++) {
                s[i][j] = __expf(s[i][j] - nm);
                sum += s[i][j];
            }
#pragma unroll
            for (int off = 8; off; off >>= 1)
                sum += __shfl_xor_sync(0xffffffffu, sum, off);
            l[i] = l[i] * alpha + sum;
#pragma unroll
            for (int j = 0; j < 4; j++) o[i][j] *= alpha;
        }

#pragma unroll
        for (int j = 0; j < 4; j++)
#pragma unroll
            for (int i = 0; i < 8; i++)
                Ps[(tx * 4 + j) * 132 + ty * 8 + i] = s[i][j];
        __syncthreads();

#pragma unroll 8
        for (int kk = 0; kk < 64; kk++) {
            float a[8], b[4];
            *(float4*)&a[0] = *(const float4*)&Ps[kk * 132 + ty * 8];
            *(float4*)&a[4] = *(const float4*)&Ps[kk * 132 + ty * 8 + 4];
            *(float4*)&b[0] = *(const float4*)&Vs[kk * 68 + tx * 4];
#pragma unroll
            for (int i = 0; i < 8; i++)
#pragma unroll
                for (int j = 0; j < 4; j++)
                    o[i][j] = fmaf(a[i], b[j], o[i][j]);
        }
    }

    const int b = bh >> 3, h = bh & 7;
#pragma unroll
    for (int i = 0; i < 8; i++) {
        const float inv = 1.0f / l[i];
        const int srow = q0 + ty * 8 + i;
        float4 r;
        r.x = o[i][0] * inv; r.y = o[i][1] * inv;
        r.z = o[i][2] * inv; r.w = o[i][3] * inv;
        *(float4*)&g_O[(b * S_LEN + srow) * D_MODEL + h * 64 + tx * 4] = r;
    }
}

// ---------------------------------------------------------------------------
extern "C" void kernel_launch(void* const* d_in, const int* in_sizes, int n_in,
                              void* d_out, int out_size)
{
    const float* q   = (const float*)d_in[0];
    const float* v   = (const float*)d_in[1];
    const float* k   = (const float*)d_in[2];
    const float* w_q = (const float*)d_in[3];
    const float* b_q = (const float*)d_in[4];
    const float* w_k = (const float*)d_in[5];
    const float* b_k = (const float*)d_in[6];
    const float* w_v = (const float*)d_in[7];
    const float* b_v = (const float*)d_in[8];
    const float* w_o = (const float*)d_in[9];
    const float* b_o = (const float*)d_in[10];
    float* out = (float*)d_out;

    const int gemm_smem = 2 * 9216 * 4;              // 73,728 B
    const size_t attn_smem = 25600 * sizeof(float);  // 102,400 B
    cudaFuncSetAttribute(tf32_gemm, cudaFuncAttributeMaxDynamicSharedMemorySize,
                         gemm_smem);
    cudaFuncSetAttribute(attn_kernel, cudaFuncAttributeMaxDynamicSharedMemorySize,
                         (int)attn_smem);

    // 1) Q/K/V projections (tf32 mma.sync, 3xTF32 compensated)
    tf32_gemm<<<dim3(D_MODEL / 128, MROWS / 128, 3), 256, gemm_smem>>>(
        q, k, v, w_q, b_q, w_k, b_k, w_v, b_v, nullptr, 0);
    // 2) Flash attention (FFMA, unchanged)
    attn_kernel<<<dim3(S_LEN / 128, BHCNT), dim3(16, 16), attn_smem>>>();
    // 3) Output projection (tf32 mma.sync)
    tf32_gemm<<<dim3(D_MODEL / 128, MROWS / 128, 1), 256, gemm_smem>>>(
        nullptr, nullptr, nullptr, w_o, b_o, nullptr, nullptr, nullptr, nullptr,
        out, 1);
}

// round 8
// speedup vs baseline: 3.2675x; 1.7130x over previous
#include <cuda_runtime.h>
#include <cuda_bf16.h>
#include <cstdint>

// Problem constants
#define D_MODEL 512
#define S_LEN   2048
#define NB      2
#define NH      8
#define DK      64
#define MROWS   (NB * S_LEN)    // 4096
#define BHCNT   (NB * NH)       // 16

// Scratch (static device globals: allocation-free, graph-capturable)
__device__ float g_Q[BHCNT * S_LEN * DK];   // head-split, pre-scaled by 1/8
__device__ float g_K[BHCNT * S_LEN * DK];
__device__ float g_V[BHCNT * S_LEN * DK];
__device__ float g_O[MROWS * D_MODEL];      // merged-head attention output

// ===========================================================================
// Helpers: legacy-path MMA (PTX ISA sm_80+, no 'a'-features) + cp.async
// ===========================================================================
__device__ __forceinline__ void mma_tf32(float* d, const uint32_t* a, const uint32_t* b)
{
    asm volatile(
        "mma.sync.aligned.m16n8k8.row.col.f32.tf32.tf32.f32 "
        "{%0,%1,%2,%3}, {%4,%5,%6,%7}, {%8,%9}, {%0,%1,%2,%3};"
        : "+f"(d[0]), "+f"(d[1]), "+f"(d[2]), "+f"(d[3])
        : "r"(a[0]), "r"(a[1]), "r"(a[2]), "r"(a[3]), "r"(b[0]), "r"(b[1]));
}

__device__ __forceinline__ void mma_bf16(float* d, const uint32_t* a, const uint32_t* b)
{
    asm volatile(
        "mma.sync.aligned.m16n8k16.row.col.f32.bf16.bf16.f32 "
        "{%0,%1,%2,%3}, {%4,%5,%6,%7}, {%8,%9}, {%0,%1,%2,%3};"
        : "+f"(d[0]), "+f"(d[1]), "+f"(d[2]), "+f"(d[3])
        : "r"(a[0]), "r"(a[1]), "r"(a[2]), "r"(a[3]), "r"(b[0]), "r"(b[1]));
}

__device__ __forceinline__ uint32_t smem_u32(const void* p) {
    uint32_t addr;
    asm("{ .reg .u64 tmp; cvta.to.shared.u64 tmp, %1; cvt.u32.u64 %0, tmp; }"
        : "=r"(addr) : "l"(p));
    return addr;
}

__device__ __forceinline__ void cp_async16(uint32_t dst, const void* src) {
    asm volatile("cp.async.cg.shared.global [%0], [%1], 16;" :: "r"(dst), "l"(src));
}
__device__ __forceinline__ void cp_commit() {
    asm volatile("cp.async.commit_group;" ::: "memory");
}
template <int N>
__device__ __forceinline__ void cp_wait() {
    asm volatile("cp.async.wait_group %0;" :: "n"(N) : "memory");
}

// Split fp32 pair -> (hi bf16x2, lo bf16x2). v.x lands in the LOW half
// (= even k index), matching the m16n8k16 fragment packing.
__device__ __forceinline__ void split_bf16x2(float x, float y, uint32_t& h, uint32_t& l)
{
    __nv_bfloat162 hb = __floats2bfloat162_rn(x, y);     // low = x, high = y
    h = *reinterpret_cast<uint32_t*>(&hb);
    float rx = x - __bfloat162float(hb.x);
    float ry = y - __bfloat162float(hb.y);
    __nv_bfloat162 lb = __floats2bfloat162_rn(rx, ry);
    l = *reinterpret_cast<uint32_t*>(&lb);
}

// ===========================================================================
// tf32 mma.sync GEMM with 3xTF32 compensation (UNCHANGED, verified R7)
// ===========================================================================
__global__ __launch_bounds__(256, 1) void tf32_gemm(
    const float* __restrict__ qx, const float* __restrict__ kx,
    const float* __restrict__ vx,
    const float* __restrict__ wq_, const float* __restrict__ bq_,
    const float* __restrict__ wk_, const float* __restrict__ bk_,
    const float* __restrict__ wv_, const float* __restrict__ bv_,
    float* __restrict__ outp, int mode)
{
    extern __shared__ __align__(16) float smf[];   // [buf][A/B][128][36]
    const uint32_t sb = smem_u32(smf);

    const float* x; const float* W; const float* bias; float* dst; float scale;
    if (mode == 0) {
        const int z = blockIdx.z;
        if (z == 0)      { x = qx; W = wq_; bias = bq_; dst = g_Q; scale = 0.125f; }
        else if (z == 1) { x = kx; W = wk_; bias = bk_; dst = g_K; scale = 1.0f; }
        else             { x = vx; W = wv_; bias = bv_; dst = g_V; scale = 1.0f; }
    } else {
        x = g_O; W = wq_; bias = bq_; dst = outp; scale = 1.0f;
    }

    const int tid = threadIdx.x;
    const int wid = tid >> 5, lid = tid & 31;
    const int g = lid >> 2, tg = lid & 3;
    const int mwarp = wid & 1, nwarp = wid >> 1;     // 2 x 4 warp grid
    const int m0 = blockIdx.y * 128, n0 = blockIdx.x * 128;

    auto load_chunk = [&](int buf, int chunk) {
        const int k0 = chunk * 32;
#pragma unroll
        for (int t = 0; t < 8; t++) {
            const int f = tid + 256 * t;     // 0..2047
            const int isB = f >> 10;
            const int g2 = f & 1023;
            const int r = g2 >> 3, q = g2 & 7;
            const float* src = isB ? &W[(size_t)(n0 + r) * D_MODEL + k0 + q * 4]
                                   : &x[(size_t)(m0 + r) * D_MODEL + k0 + q * 4];
            const uint32_t doff = (uint32_t)(buf * 9216 + isB * 4608 + r * 36 + q * 4) * 4u;
            cp_async16(sb + doff, src);
        }
    };

    float acc[4][4][4];
#pragma unroll
    for (int i = 0; i < 4; i++)
#pragma unroll
        for (int j = 0; j < 4; j++)
#pragma unroll
            for (int e = 0; e < 4; e++) acc[i][j][e] = 0.0f;

    load_chunk(0, 0);
    cp_commit();

    for (int c = 0; c < 16; c++) {
        const int buf = c & 1;
        if (c < 15) {
            load_chunk(buf ^ 1, c + 1);
            cp_commit();
            cp_wait<1>();
        } else {
            cp_wait<0>();
        }
        __syncthreads();

        const float* Ab = smf + buf * 9216;
        const float* Bb = Ab + 4608;
#pragma unroll
        for (int ks = 0; ks < 32; ks += 8) {
            uint32_t ah[4][4], al[4][4];
#pragma unroll
            for (int i = 0; i < 4; i++) {
                const int r0 = mwarp * 64 + i * 16 + g;
                const float v0 = Ab[r0 * 36 + ks + tg];
                const float v1 = Ab[(r0 + 8) * 36 + ks + tg];
                const float v2 = Ab[r0 * 36 + ks + tg + 4];
                const float v3 = Ab[(r0 + 8) * 36 + ks + tg + 4];
                ah[i][0] = __float_as_uint(v0) & 0xFFFFE000u;
                ah[i][1] = __float_as_uint(v1) & 0xFFFFE000u;
                ah[i][2] = __float_as_uint(v2) & 0xFFFFE000u;
                ah[i][3] = __float_as_uint(v3) & 0xFFFFE000u;
                al[i][0] = __float_as_uint(v0 - __uint_as_float(ah[i][0]));
                al[i][1] = __float_as_uint(v1 - __uint_as_float(ah[i][1]));
                al[i][2] = __float_as_uint(v2 - __uint_as_float(ah[i][2]));
                al[i][3] = __float_as_uint(v3 - __uint_as_float(ah[i][3]));
            }
            uint32_t bh[4][2], bl[4][2];
#pragma unroll
            for (int j = 0; j < 4; j++) {
                const int rn = nwarp * 32 + j * 8 + g;
                const float v0 = Bb[rn * 36 + ks + tg];
                const float v1 = Bb[rn * 36 + ks + tg + 4];
                bh[j][0] = __float_as_uint(v0) & 0xFFFFE000u;
                bh[j][1] = __float_as_uint(v1) & 0xFFFFE000u;
                bl[j][0] = __float_as_uint(v0 - __uint_as_float(bh[j][0]));
                bl[j][1] = __float_as_uint(v1 - __uint_as_float(bh[j][1]));
            }
#pragma unroll
            for (int i = 0; i < 4; i++)
#pragma unroll
                for (int j = 0; j < 4; j++) {
                    mma_tf32(acc[i][j], ah[i], bh[j]);
                    mma_tf32(acc[i][j], al[i], bh[j]);
                    mma_tf32(acc[i][j], ah[i], bl[j]);
                }
        }
        __syncthreads();
    }

#pragma unroll
    for (int j = 0; j < 4; j++) {
        const int n = n0 + nwarp * 32 + j * 8 + 2 * tg;
        const float bv0 = __ldg(&bias[n]), bv1 = __ldg(&bias[n + 1]);
#pragma unroll
        for (int i = 0; i < 4; i++) {
            const int mA = m0 + mwarp * 64 + i * 16 + g;
            const int mB = mA + 8;
            float2 r0, r1;
            r0.x = (acc[i][j][0] + bv0) * scale;
            r0.y = (acc[i][j][1] + bv1) * scale;
            r1.x = (acc[i][j][2] + bv0) * scale;
            r1.y = (acc[i][j][3] + bv1) * scale;
            if (mode == 0) {
                const int h = n >> 6, dk = n & 63;
                const int bA = mA >> 11, sA = mA & (S_LEN - 1);
                const int bB = mB >> 11, sB = mB & (S_LEN - 1);
                *(float2*)&dst[((size_t)(bA * NH + h) * S_LEN + sA) * DK + dk] = r0;
                *(float2*)&dst[((size_t)(bB * NH + h) * S_LEN + sB) * DK + dk] = r1;
            } else {
                *(float2*)&dst[(size_t)mA * D_MODEL + n] = r0;
                *(float2*)&dst[(size_t)mB * D_MODEL + n] = r1;
            }
        }
    }
}

// ===========================================================================
// bf16 mma.sync flash attention with 3xBF16 compensation.
//   Per CTA: (bh, 128-q-tile). 8 warps, warp w owns q-rows w*16..w*16+15.
//   K/V chunks of 64 keys, raw fp32 double-buffered via cp.async, split to
//   packed bf16x2 hi/lo in smem. P staged per-warp through smem (acc->A-frag
//   layout conversion), no block sync needed between softmax and PV.
//
// SMEM map (uint32 offsets):
//   Qh 0      [128 q][36]  (32 d-pairs + pad)   Ql  4608
//   Kh 9216   [64 key][36] (32 d-pairs + pad)   Kl 11520
//   Vh 13824  [32 keypair][72] (64 d + pad)     Vl 16128
//   Ph 18432  [128 q][36]  (32 key-pairs + pad) Pl 23040
//   RAW 27648 [2][8192]  raw K[64][64] + V[64][64] fp32
// Total 44032 u32 = 176128 B.
// ===========================================================================
#define A_QH 0
#define A_QL 4608
#define A_KH 9216
#define A_KL 11520
#define A_VH 13824
#define A_VL 16128
#define A_PH 18432
#define A_PL 23040
#define A_RAW 27648

__global__ __launch_bounds__(256, 1) void attn_mma()
{
    extern __shared__ __align__(16) uint32_t sm[];
    float* smf = (float*)sm;
    const uint32_t sb = smem_u32(sm);

    const int tid = threadIdx.x;
    const int wid = tid >> 5, lid = tid & 31;
    const int g = lid >> 2, tg = lid & 3;
    const int bh = blockIdx.y;
    const int q0 = blockIdx.x * 128;
    const int qr = wid * 16;

    const float* Qg = g_Q + ((size_t)bh * S_LEN + q0) * DK;
    const float* Kg = g_K + (size_t)bh * S_LEN * DK;
    const float* Vg = g_V + (size_t)bh * S_LEN * DK;

    // Prefetch raw K/V chunk 0 (16 KB K + 16 KB V)
#pragma unroll
    for (int t = 0; t < 8; t++) {
        const int f = tid + 256 * t;                       // 0..2047 x 16B
        const float* src = (f < 1024) ? (Kg + (size_t)f * 4)
                                      : (Vg + (size_t)(f - 1024) * 4);
        cp_async16(sb + (uint32_t)(A_RAW + f * 4) * 4u, src);
    }
    cp_commit();

    // Load + split Q once (reused for all 32 chunks)
#pragma unroll
    for (int t = 0; t < 16; t++) {
        const int idx = tid + 256 * t;                     // 0..4095 pairs
        const int r = idx >> 5, kp = idx & 31;
        const float2 v = *(const float2*)(Qg + (size_t)r * 64 + kp * 2);
        uint32_t h, l;
        split_bf16x2(v.x, v.y, h, l);
        sm[A_QH + r * 36 + kp] = h;
        sm[A_QL + r * 36 + kp] = l;
    }

    float m0 = -1e30f, m1 = -1e30f, l0 = 0.0f, l1 = 0.0f;
    float o[8][4];
#pragma unroll
    for (int nt = 0; nt < 8; nt++)
#pragma unroll
        for (int e = 0; e < 4; e++) o[nt][e] = 0.0f;

    for (int kt = 0; kt < S_LEN / 64; kt++) {
        const int buf = kt & 1;
        const uint32_t rawo = A_RAW + (uint32_t)buf * 8192u;

        // Prefetch next chunk into the other raw buffer, then wait for this one
        if (kt + 1 < S_LEN / 64) {
            const float* Kn = Kg + (size_t)(kt + 1) * 64 * 64;
            const float* Vn = Vg + (size_t)(kt + 1) * 64 * 64;
#pragma unroll
            for (int t = 0; t < 8; t++) {
                const int f = tid + 256 * t;
                const float* src = (f < 1024) ? (Kn + (size_t)f * 4)
                                              : (Vn + (size_t)(f - 1024) * 4);
                cp_async16(sb + (uint32_t)(A_RAW + (buf ^ 1) * 8192 + f * 4) * 4u, src);
            }
            cp_commit();
            cp_wait<1>();
        } else {
            cp_wait<0>();
        }
        __syncthreads();   // raw[buf] ready AND all warps done with packed bufs

        // Split K: [key][d-pair] -> Kh/Kl[key][36]
#pragma unroll
        for (int t = 0; t < 8; t++) {
            const int idx = tid + 256 * t;                 // 0..2047
            const int n = idx >> 5, kp = idx & 31;
            const float2 v = *(const float2*)(smf + rawo + n * 64 + kp * 2);
            uint32_t h, l;
            split_bf16x2(v.x, v.y, h, l);
            sm[A_KH + n * 36 + kp] = h;
            sm[A_KL + n * 36 + kp] = l;
        }
        // Split V: key-pairs packed per d -> Vh/Vl[keypair][72]
#pragma unroll
        for (int t = 0; t < 8; t++) {
            const int idx = tid + 256 * t;                 // 0..2047
            const int kp = idx >> 6, d = idx & 63;
            const float vx = smf[rawo + 4096 + (2 * kp) * 64 + d];
            const float vy = smf[rawo + 4096 + (2 * kp + 1) * 64 + d];
            uint32_t h, l;
            split_bf16x2(vx, vy, h, l);
            sm[A_VH + kp * 72 + d] = h;
            sm[A_VL + kp * 72 + d] = l;
        }
        __syncthreads();

        // ---- S = Q K^T (3xBF16) ----
        float s[8][4];
#pragma unroll
        for (int nt = 0; nt < 8; nt++)
#pragma unroll
            for (int e = 0; e < 4; e++) s[nt][e] = 0.0f;

#pragma unroll
        for (int kc = 0; kc < 4; kc++) {
            const int ra = (qr + g) * 36 + kc * 8;
            const int rb = (qr + g + 8) * 36 + kc * 8;
            uint32_t aH[4], aL[4];
            aH[0] = sm[A_QH + ra + tg];     aH[1] = sm[A_QH + rb + tg];
            aH[2] = sm[A_QH + ra + tg + 4]; aH[3] = sm[A_QH + rb + tg + 4];
            aL[0] = sm[A_QL + ra + tg];     aL[1] = sm[A_QL + rb + tg];
            aL[2] = sm[A_QL + ra + tg + 4]; aL[3] = sm[A_QL + rb + tg + 4];
#pragma unroll
            for (int nt = 0; nt < 8; nt++) {
                const int nb = (nt * 8 + g) * 36 + kc * 8;
                uint32_t bH[2], bL[2];
                bH[0] = sm[A_KH + nb + tg]; bH[1] = sm[A_KH + nb + tg + 4];
                bL[0] = sm[A_KL + nb + tg]; bL[1] = sm[A_KL + nb + tg + 4];
                mma_bf16(s[nt], aH, bH);
                mma_bf16(s[nt], aL, bH);
                mma_bf16(s[nt], aH, bL);
            }
        }

        // ---- online softmax (rows g and g+8; quad = lanes sharing g) ----
        {
            float mx0 = -1e30f, mx1 = -1e30f;
#pragma unroll
            for (int nt = 0; nt < 8; nt++) {
                mx0 = fmaxf(mx0, fmaxf(s[nt][0], s[nt][1]));
                mx1 = fmaxf(mx1, fmaxf(s[nt][2], s[nt][3]));
            }
            mx0 = fmaxf(mx0, __shfl_xor_sync(0xffffffffu, mx0, 1));
            mx0 = fmaxf(mx0, __shfl_xor_sync(0xffffffffu, mx0, 2));
            mx1 = fmaxf(mx1, __shfl_xor_sync(0xffffffffu, mx1, 1));
            mx1 = fmaxf(mx1, __shfl_xor_sync(0xffffffffu, mx1, 2));
            const float nm0 = fmaxf(m0, mx0), nm1 = fmaxf(m1, mx1);
            const float al0 = __expf(m0 - nm0), al1 = __expf(m1 - nm1);
            m0 = nm0; m1 = nm1;
            float sum0 = 0.0f, sum1 = 0.0f;
#pragma unroll
            for (int nt = 0; nt < 8; nt++) {
                s[nt][0] = __expf(s[nt][0] - nm0);
                s[nt][1] = __expf(s[nt][1] - nm0);
                s[nt][2] = __expf(s[nt][2] - nm1);
                s[nt][3] = __expf(s[nt][3] - nm1);
                sum0 += s[nt][0] + s[nt][1];
                sum1 += s[nt][2] + s[nt][3];
            }
            sum0 += __shfl_xor_sync(0xffffffffu, sum0, 1);
            sum0 += __shfl_xor_sync(0xffffffffu, sum0, 2);
            sum1 += __shfl_xor_sync(0xffffffffu, sum1, 1);
            sum1 += __shfl_xor_sync(0xffffffffu, sum1, 2);
            l0 = l0 * al0 + sum0;
            l1 = l1 * al1 + sum1;
#pragma unroll
            for (int nt = 0; nt < 8; nt++) {
                o[nt][0] *= al0; o[nt][1] *= al0;
                o[nt][2] *= al1; o[nt][3] *= al1;
            }
        }

        // ---- stage P (hi/lo bf16x2) for this warp's own rows ----
#pragma unroll
        for (int nt = 0; nt < 8; nt++) {
            uint32_t h0, lo0, h1, lo1;
            split_bf16x2(s[nt][0], s[nt][1], h0, lo0);
            split_bf16x2(s[nt][2], s[nt][3], h1, lo1);
            const int kp = nt * 4 + tg;
            sm[A_PH + (qr + g) * 36 + kp]     = h0;
            sm[A_PL + (qr + g) * 36 + kp]     = lo0;
            sm[A_PH + (qr + g + 8) * 36 + kp] = h1;
            sm[A_PL + (qr + g + 8) * 36 + kp] = lo1;
        }
        __syncwarp();

        // ---- O += P V (3xBF16) ----
#pragma unroll
        for (int kc = 0; kc < 4; kc++) {
            const int ra = (qr + g) * 36 + kc * 8;
            const int rb = (qr + g + 8) * 36 + kc * 8;
            uint32_t aH[4], aL[4];
            aH[0] = sm[A_PH + ra + tg];     aH[1] = sm[A_PH + rb + tg];
            aH[2] = sm[A_PH + ra + tg + 4]; aH[3] = sm[A_PH + rb + tg + 4];
            aL[0] = sm[A_PL + ra + tg];     aL[1] = sm[A_PL + rb + tg];
            aL[2] = sm[A_PL + ra + tg + 4]; aL[3] = sm[A_PL + rb + tg + 4];
#pragma unroll
            for (int nt = 0; nt < 8; nt++) {
                const int c0 = (kc * 8 + tg) * 72 + nt * 8 + g;
                const int c1 = (kc * 8 + tg + 4) * 72 + nt * 8 + g;
                uint32_t bH[2], bL[2];
                bH[0] = sm[A_VH + c0]; bH[1] = sm[A_VH + c1];
                bL[0] = sm[A_VL + c0]; bL[1] = sm[A_VL + c1];
                mma_bf16(o[nt], aH, bH);
                mma_bf16(o[nt], aL, bH);
                mma_bf16(o[nt], aH, bL);
            }
        }
    }

    // ---- normalize + write merged-head layout ----
    const int b = bh >> 3, h = bh & 7;
    const float inv0 = 1.0f / l0, inv1 = 1.0f / l1;
    const int row0 = q0 + qr + g, row1 = row0 + 8;
#pragma unroll
    for (int nt = 0; nt < 8; nt++) {
        const int col = h * 64 + nt * 8 + tg * 2;
        float2 r0, r1;
        r0.x = o[nt][0] * inv0; r0.y = o[nt][1] * inv0;
        r1.x = o[nt][2] * inv1; r1.y = o[nt][3] * inv1;
        *(float2*)&g_O[(size_t)(b * S_LEN + row0) * D_MODEL + col] = r0;
        *(float2*)&g_O[(size_t)(b * S_LEN + row1) * D_MODEL + col] = r1;
    }
}

// ---------------------------------------------------------------------------
extern "C" void kernel_launch(void* const* d_in, const int* in_sizes, int n_in,
                              void* d_out, int out_size)
{
    const float* q   = (const float*)d_in[0];
    const float* v   = (const float*)d_in[1];
    const float* k   = (const float*)d_in[2];
    const float* w_q = (const float*)d_in[3];
    const float* b_q = (const float*)d_in[4];
    const float* w_k = (const float*)d_in[5];
    const float* b_k = (const float*)d_in[6];
    const float* w_v = (const float*)d_in[7];
    const float* b_v = (const float*)d_in[8];
    const float* w_o = (const float*)d_in[9];
    const float* b_o = (const float*)d_in[10];
    float* out = (float*)d_out;

    const int gemm_smem = 2 * 9216 * 4;     // 73,728 B
    const int attn_smem = 44032 * 4;        // 176,128 B
    cudaFuncSetAttribute(tf32_gemm, cudaFuncAttributeMaxDynamicSharedMemorySize,
                         gemm_smem);
    cudaFuncSetAttribute(attn_mma, cudaFuncAttributeMaxDynamicSharedMemorySize,
                         attn_smem);

    // 1) Q/K/V projections (tf32 mma.sync, 3xTF32 compensated)
    tf32_gemm<<<dim3(D_MODEL / 128, MROWS / 128, 3), 256, gemm_smem>>>(
        q, k, v, w_q, b_q, w_k, b_k, w_v, b_v, nullptr, 0);
    // 2) Flash attention (bf16 mma.sync, 3xBF16 compensated)
    attn_mma<<<dim3(S_LEN / 128, BHCNT), 256, attn_smem>>>();
    // 3) Output projection (tf32 mma.sync)
    tf32_gemm<<<dim3(D_MODEL / 128, MROWS / 128, 1), 256, gemm_smem>>>(
        nullptr, nullptr, nullptr, w_o, b_o, nullptr, nullptr, nullptr, nullptr,
        out, 1);
}

// round 9
// speedup vs baseline: 3.7966x; 1.1619x over previous
#include <cuda_runtime.h>
#include <cuda_bf16.h>
#include <cstdint>

// Problem constants
#define D_MODEL 512
#define S_LEN   2048
#define NB      2
#define NH      8
#define DK      64
#define MROWS   (NB * S_LEN)    // 4096
#define BHCNT   (NB * NH)       // 16
#define PAIRS   (DK / 2)        // 32 u32 per row

// Scratch (static device globals: allocation-free, graph-capturable)
// bf16 hi/lo planes, pair-packed (u32 = bf16[even d], bf16[odd d]), head-split
__device__ uint32_t g_Qh[BHCNT * S_LEN * PAIRS];
__device__ uint32_t g_Ql[BHCNT * S_LEN * PAIRS];
__device__ uint32_t g_Kh[BHCNT * S_LEN * PAIRS];
__device__ uint32_t g_Kl[BHCNT * S_LEN * PAIRS];
__device__ uint32_t g_Vh[BHCNT * S_LEN * PAIRS];
__device__ uint32_t g_Vl[BHCNT * S_LEN * PAIRS];
__device__ float    g_O[MROWS * D_MODEL];      // merged-head attention output

// ===========================================================================
// Helpers: legacy-path MMA (PTX ISA sm_80+, no 'a'-features) + cp.async
// ===========================================================================
__device__ __forceinline__ void mma_bf16(float* d, const uint32_t* a, const uint32_t* b)
{
    asm volatile(
        "mma.sync.aligned.m16n8k16.row.col.f32.bf16.bf16.f32 "
        "{%0,%1,%2,%3}, {%4,%5,%6,%7}, {%8,%9}, {%0,%1,%2,%3};"
        : "+f"(d[0]), "+f"(d[1]), "+f"(d[2]), "+f"(d[3])
        : "r"(a[0]), "r"(a[1]), "r"(a[2]), "r"(a[3]), "r"(b[0]), "r"(b[1]));
}

__device__ __forceinline__ void ldsm_x2_trans(uint32_t& r0, uint32_t& r1, uint32_t addr)
{
    asm volatile("ldmatrix.sync.aligned.m8n8.x2.trans.shared.b16 {%0,%1}, [%2];"
                 : "=r"(r0), "=r"(r1) : "r"(addr));
}

__device__ __forceinline__ uint32_t smem_u32(const void* p) {
    uint32_t addr;
    asm("{ .reg .u64 tmp; cvta.to.shared.u64 tmp, %1; cvt.u32.u64 %0, tmp; }"
        : "=r"(addr) : "l"(p));
    return addr;
}

__device__ __forceinline__ void cp_async16(uint32_t dst, const void* src) {
    asm volatile("cp.async.cg.shared.global [%0], [%1], 16;" :: "r"(dst), "l"(src));
}
__device__ __forceinline__ void cp_commit() {
    asm volatile("cp.async.commit_group;" ::: "memory");
}
template <int N>
__device__ __forceinline__ void cp_wait() {
    asm volatile("cp.async.wait_group %0;" :: "n"(N) : "memory");
}

// Split fp32 pair -> (hi bf16x2, lo bf16x2). v.x lands in the LOW half
// (= even index), matching mma fragment packing and memory pair order.
__device__ __forceinline__ void split_bf16x2(float x, float y, uint32_t& h, uint32_t& l)
{
    __nv_bfloat162 hb = __floats2bfloat162_rn(x, y);
    h = *reinterpret_cast<uint32_t*>(&hb);
    float rx = x - __bfloat162float(hb.x);
    float ry = y - __bfloat162float(hb.y);
    __nv_bfloat162 lb = __floats2bfloat162_rn(rx, ry);
    l = *reinterpret_cast<uint32_t*>(&lb);
}

// ===========================================================================
// bf16 mma.sync GEMM with 3xBF16 compensation: out = x @ W^T + bias
//   CTA tile 128x128, 8 warps (2x4), warp tile 64x32 (4x4 m16n8k16 tiles).
//   K chunks of 32 (2 k16 steps), double-buffered cp.async; raw fp32 smem,
//   hi/lo split at fragment-load time.
//   mode 0: z selects Q/K/V; epilogue splits result to bf16 hi/lo planes,
//           head-split layout (Q scaled 0.125).
//   mode 1: x = g_O, W/bias from wq_/bq_ params, fp32 [4096,512] output.
// ===========================================================================
__global__ __launch_bounds__(256, 1) void bf16_gemm(
    const float* __restrict__ qx, const float* __restrict__ kx,
    const float* __restrict__ vx,
    const float* __restrict__ wq_, const float* __restrict__ bq_,
    const float* __restrict__ wk_, const float* __restrict__ bk_,
    const float* __restrict__ wv_, const float* __restrict__ bv_,
    float* __restrict__ outp, int mode)
{
    extern __shared__ __align__(16) float smf[];   // [buf][A/B][128][36]
    const uint32_t sb = smem_u32(smf);

    const float* x; const float* W; const float* bias; float scale;
    uint32_t* dh = nullptr; uint32_t* dl = nullptr;
    if (mode == 0) {
        const int z = blockIdx.z;
        if (z == 0)      { x = qx; W = wq_; bias = bq_; dh = g_Qh; dl = g_Ql; scale = 0.125f; }
        else if (z == 1) { x = kx; W = wk_; bias = bk_; dh = g_Kh; dl = g_Kl; scale = 1.0f; }
        else             { x = vx; W = wv_; bias = bv_; dh = g_Vh; dl = g_Vl; scale = 1.0f; }
    } else {
        x = g_O; W = wq_; bias = bq_; scale = 1.0f;
    }

    const int tid = threadIdx.x;
    const int wid = tid >> 5, lid = tid & 31;
    const int g = lid >> 2, tg = lid & 3;
    const int mwarp = wid & 1, nwarp = wid >> 1;     // 2 x 4 warp grid
    const int m0 = blockIdx.y * 128, n0 = blockIdx.x * 128;

    auto load_chunk = [&](int buf, int chunk) {
        const int k0 = chunk * 32;
#pragma unroll
        for (int t = 0; t < 8; t++) {
            const int f = tid + 256 * t;     // 0..2047
            const int isB = f >> 10;
            const int g2 = f & 1023;
            const int r = g2 >> 3, q = g2 & 7;
            const float* src = isB ? &W[(size_t)(n0 + r) * D_MODEL + k0 + q * 4]
                                   : &x[(size_t)(m0 + r) * D_MODEL + k0 + q * 4];
            const uint32_t doff = (uint32_t)(buf * 9216 + isB * 4608 + r * 36 + q * 4) * 4u;
            cp_async16(sb + doff, src);
        }
    };

    float acc[4][4][4];
#pragma unroll
    for (int i = 0; i < 4; i++)
#pragma unroll
        for (int j = 0; j < 4; j++)
#pragma unroll
            for (int e = 0; e < 4; e++) acc[i][j][e] = 0.0f;

    load_chunk(0, 0);
    cp_commit();

    for (int c = 0; c < 16; c++) {
        const int buf = c & 1;
        if (c < 15) {
            load_chunk(buf ^ 1, c + 1);
            cp_commit();
            cp_wait<1>();
        } else {
            cp_wait<0>();
        }
        __syncthreads();

        const float* Ab = smf + buf * 9216;
        const float* Bb = Ab + 4608;
#pragma unroll
        for (int ks = 0; ks < 32; ks += 16) {
            uint32_t ah[4][4], al[4][4];
#pragma unroll
            for (int i = 0; i < 4; i++) {
                const int r0 = mwarp * 64 + i * 16 + g;
                const float2 v0 = *(const float2*)&Ab[r0 * 36 + ks + tg * 2];
                const float2 v1 = *(const float2*)&Ab[(r0 + 8) * 36 + ks + tg * 2];
                const float2 v2 = *(const float2*)&Ab[r0 * 36 + ks + tg * 2 + 8];
                const float2 v3 = *(const float2*)&Ab[(r0 + 8) * 36 + ks + tg * 2 + 8];
                split_bf16x2(v0.x, v0.y, ah[i][0], al[i][0]);
                split_bf16x2(v1.x, v1.y, ah[i][1], al[i][1]);
                split_bf16x2(v2.x, v2.y, ah[i][2], al[i][2]);
                split_bf16x2(v3.x, v3.y, ah[i][3], al[i][3]);
            }
            uint32_t bh[4][2], bl[4][2];
#pragma unroll
            for (int j = 0; j < 4; j++) {
                const int rn = nwarp * 32 + j * 8 + g;
                const float2 v0 = *(const float2*)&Bb[rn * 36 + ks + tg * 2];
                const float2 v1 = *(const float2*)&Bb[rn * 36 + ks + tg * 2 + 8];
                split_bf16x2(v0.x, v0.y, bh[j][0], bl[j][0]);
                split_bf16x2(v1.x, v1.y, bh[j][1], bl[j][1]);
            }
#pragma unroll
            for (int i = 0; i < 4; i++)
#pragma unroll
                for (int j = 0; j < 4; j++) {
                    mma_bf16(acc[i][j], ah[i], bh[j]);
                    mma_bf16(acc[i][j], al[i], bh[j]);
                    mma_bf16(acc[i][j], ah[i], bl[j]);
                }
        }
        __syncthreads();
    }

    // ---- epilogue ----
#pragma unroll
    for (int j = 0; j < 4; j++) {
        const int n = n0 + nwarp * 32 + j * 8 + 2 * tg;      // even
        const float bv0 = __ldg(&bias[n]), bv1 = __ldg(&bias[n + 1]);
#pragma unroll
        for (int i = 0; i < 4; i++) {
            const int mA = m0 + mwarp * 64 + i * 16 + g;
            const int mB = mA + 8;
            const float v0 = (acc[i][j][0] + bv0) * scale;
            const float v1 = (acc[i][j][1] + bv1) * scale;
            const float v2 = (acc[i][j][2] + bv0) * scale;
            const float v3 = (acc[i][j][3] + bv1) * scale;
            if (mode == 0) {
                const int h = n >> 6, dkp = (n & 63) >> 1;
                const int bA = mA >> 11, sA = mA & (S_LEN - 1);
                const int bB = mB >> 11, sB = mB & (S_LEN - 1);
                uint32_t hh, ll;
                split_bf16x2(v0, v1, hh, ll);
                const size_t iA = ((size_t)(bA * NH + h) * S_LEN + sA) * PAIRS + dkp;
                dh[iA] = hh; dl[iA] = ll;
                split_bf16x2(v2, v3, hh, ll);
                const size_t iB = ((size_t)(bB * NH + h) * S_LEN + sB) * PAIRS + dkp;
                dh[iB] = hh; dl[iB] = ll;
            } else {
                *(float2*)&outp[(size_t)mA * D_MODEL + n] = make_float2(v0, v1);
                *(float2*)&outp[(size_t)mB * D_MODEL + n] = make_float2(v2, v3);
            }
        }
    }
}

// ===========================================================================
// bf16 mma.sync flash attention, 3xBF16, pre-split inputs.
//   Per CTA: (bh, 128-q-tile). 8 warps, warp w owns q-rows w*16..w*16+15.
//   K/V chunks of 64 keys; hi/lo bf16 planes cp.async'd directly into
//   mma-ready row-major smem. V B-fragments via ldmatrix.trans.
//   One __syncthreads per chunk (wait -> sync -> prefetch -> compute).
//
// SMEM map (u32 offsets), all rows padded to 36 u32 (144 B):
//   QH 0     [128][36]   QL 4608
//   KH(buf)  9216  + buf*2304   [64][36]
//   KL(buf)  13824 + buf*2304
//   VH(buf)  18432 + buf*2304
//   VL(buf)  23040 + buf*2304
//   PH 27648 [128][36]   PL 32256
// Total 36864 u32 = 147,456 B
// ===========================================================================
#define AQ_H 0
#define AQ_L 4608
#define AK_H(b) (9216  + (b) * 2304)
#define AK_L(b) (13824 + (b) * 2304)
#define AV_H(b) (18432 + (b) * 2304)
#define AV_L(b) (23040 + (b) * 2304)
#define AP_H 27648
#define AP_L 32256

__global__ __launch_bounds__(256, 1) void attn_mma()
{
    extern __shared__ __align__(16) uint32_t sm[];
    const uint32_t sb = smem_u32(sm);

    const int tid = threadIdx.x;
    const int wid = tid >> 5, lid = tid & 31;
    const int g = lid >> 2, tg = lid & 3;
    const int bh = blockIdx.y;
    const int q0 = blockIdx.x * 128;
    const int qr = wid * 16;

    const uint32_t* Qh = g_Qh + ((size_t)bh * S_LEN + q0) * PAIRS;
    const uint32_t* Ql = g_Ql + ((size_t)bh * S_LEN + q0) * PAIRS;
    const uint32_t* Kh = g_Kh + (size_t)bh * S_LEN * PAIRS;
    const uint32_t* Kl = g_Kl + (size_t)bh * S_LEN * PAIRS;
    const uint32_t* Vh = g_Vh + (size_t)bh * S_LEN * PAIRS;
    const uint32_t* Vl = g_Vl + (size_t)bh * S_LEN * PAIRS;

    // K/V chunk loader: 4 planes x 64 rows x 8 x 16B = 2048 chunks
    auto load_kv = [&](int buf, int kt) {
        const size_t base = (size_t)kt * 64 * PAIRS;
#pragma unroll
        for (int t = 0; t < 8; t++) {
            const int f = tid + 256 * t;
            const int plane = f >> 9;                 // 0:KH 1:KL 2:VH 3:VL
            const int rem = f & 511;
            const int r = rem >> 3, cc = rem & 7;
            const uint32_t* src;
            uint32_t dst;
            const size_t so = base + (size_t)r * PAIRS + cc * 4;
            if (plane == 0)      { src = Kh + so; dst = AK_H(buf); }
            else if (plane == 1) { src = Kl + so; dst = AK_L(buf); }
            else if (plane == 2) { src = Vh + so; dst = AV_H(buf); }
            else                 { src = Vl + so; dst = AV_L(buf); }
            cp_async16(sb + (dst + (uint32_t)(r * 36 + cc * 4)) * 4u, src);
        }
    };

    // Q (2 planes x 128 rows x 8) + chunk 0, one group
#pragma unroll
    for (int t = 0; t < 8; t++) {
        const int f = tid + 256 * t;                  // 0..2047
        const int plane = f >> 10;
        const int rem = f & 1023;
        const int r = rem >> 3, cc = rem & 7;
        const uint32_t* src = (plane ? Ql : Qh) + (size_t)r * PAIRS + cc * 4;
        const uint32_t dst = (plane ? AQ_L : AQ_H) + (uint32_t)(r * 36 + cc * 4);
        cp_async16(sb + dst * 4u, src);
    }
    load_kv(0, 0);
    cp_commit();

    float m0 = -1e30f, m1 = -1e30f, l0 = 0.0f, l1 = 0.0f;
    float o[8][4];
#pragma unroll
    for (int nt = 0; nt < 8; nt++)
#pragma unroll
        for (int e = 0; e < 4; e++) o[nt][e] = 0.0f;

    for (int kt = 0; kt < S_LEN / 64; kt++) {
        const int buf = kt & 1;
        cp_wait<0>();
        __syncthreads();        // data visible; prev readers of buf^1 done
        if (kt + 1 < S_LEN / 64) {
            load_kv(buf ^ 1, kt + 1);
            cp_commit();
        }

        // ---- S = Q K^T (3xBF16) ----
        float s[8][4];
#pragma unroll
        for (int nt = 0; nt < 8; nt++)
#pragma unroll
            for (int e = 0; e < 4; e++) s[nt][e] = 0.0f;

#pragma unroll
        for (int kc = 0; kc < 4; kc++) {
            const int ra = (qr + g) * 36 + kc * 8;
            const int rb = (qr + g + 8) * 36 + kc * 8;
            uint32_t aH[4], aL[4];
            aH[0] = sm[AQ_H + ra + tg];     aH[1] = sm[AQ_H + rb + tg];
            aH[2] = sm[AQ_H + ra + tg + 4]; aH[3] = sm[AQ_H + rb + tg + 4];
            aL[0] = sm[AQ_L + ra + tg];     aL[1] = sm[AQ_L + rb + tg];
            aL[2] = sm[AQ_L + ra + tg + 4]; aL[3] = sm[AQ_L + rb + tg + 4];
#pragma unroll
            for (int nt = 0; nt < 8; nt++) {
                const int nb = (nt * 8 + g) * 36 + kc * 8;
                uint32_t bH[2], bL[2];
                bH[0] = sm[AK_H(buf) + nb + tg]; bH[1] = sm[AK_H(buf) + nb + tg + 4];
                bL[0] = sm[AK_L(buf) + nb + tg]; bL[1] = sm[AK_L(buf) + nb + tg + 4];
                mma_bf16(s[nt], aH, bH);
                mma_bf16(s[nt], aL, bH);
                mma_bf16(s[nt], aH, bL);
            }
        }

        // ---- online softmax ----
        {
            float mx0 = -1e30f, mx1 = -1e30f;
#pragma unroll
            for (int nt = 0; nt < 8; nt++) {
                mx0 = fmaxf(mx0, fmaxf(s[nt][0], s[nt][1]));
                mx1 = fmaxf(mx1, fmaxf(s[nt][2], s[nt][3]));
            }
            mx0 = fmaxf(mx0, __shfl_xor_sync(0xffffffffu, mx0, 1));
            mx0 = fmaxf(mx0, __shfl_xor_sync(0xffffffffu, mx0, 2));
            mx1 = fmaxf(mx1, __shfl_xor_sync(0xffffffffu, mx1, 1));
            mx1 = fmaxf(mx1, __shfl_xor_sync(0xffffffffu, mx1, 2));
            const float nm0 = fmaxf(m0, mx0), nm1 = fmaxf(m1, mx1);
            const float al0 = __expf(m0 - nm0), al1 = __expf(m1 - nm1);
            m0 = nm0; m1 = nm1;
            float sum0 = 0.0f, sum1 = 0.0f;
#pragma unroll
            for (int nt = 0; nt < 8; nt++) {
                s[nt][0] = __expf(s[nt][0] - nm0);
                s[nt][1] = __expf(s[nt][1] - nm0);
                s[nt][2] = __expf(s[nt][2] - nm1);
                s[nt][3] = __expf(s[nt][3] - nm1);
                sum0 += s[nt][0] + s[nt][1];
                sum1 += s[nt][2] + s[nt][3];
            }
            sum0 += __shfl_xor_sync(0xffffffffu, sum0, 1);
            sum0 += __shfl_xor_sync(0xffffffffu, sum0, 2);
            sum1 += __shfl_xor_sync(0xffffffffu, sum1, 1);
            sum1 += __shfl_xor_sync(0xffffffffu, sum1, 2);
            l0 = l0 * al0 + sum0;
            l1 = l1 * al1 + sum1;
#pragma unroll
            for (int nt = 0; nt < 8; nt++) {
                o[nt][0] *= al0; o[nt][1] *= al0;
                o[nt][2] *= al1; o[nt][3] *= al1;
            }
        }

        // ---- stage P (hi/lo bf16x2), warp-local rows ----
#pragma unroll
        for (int nt = 0; nt < 8; nt++) {
            uint32_t h0, lo0, h1, lo1;
            split_bf16x2(s[nt][0], s[nt][1], h0, lo0);
            split_bf16x2(s[nt][2], s[nt][3], h1, lo1);
            const int kp = nt * 4 + tg;
            sm[AP_H + (qr + g) * 36 + kp]     = h0;
            sm[AP_L + (qr + g) * 36 + kp]     = lo0;
            sm[AP_H + (qr + g + 8) * 36 + kp] = h1;
            sm[AP_L + (qr + g + 8) * 36 + kp] = lo1;
        }
        __syncwarp();

        // ---- O += P V (3xBF16, V B-frags via ldmatrix.trans) ----
#pragma unroll
        for (int kc = 0; kc < 4; kc++) {
            const int ra = (qr + g) * 36 + kc * 8;
            const int rb = (qr + g + 8) * 36 + kc * 8;
            uint32_t aH[4], aL[4];
            aH[0] = sm[AP_H + ra + tg];     aH[1] = sm[AP_H + rb + tg];
            aH[2] = sm[AP_H + ra + tg + 4]; aH[3] = sm[AP_H + rb + tg + 4];
            aL[0] = sm[AP_L + ra + tg];     aL[1] = sm[AP_L + rb + tg];
            aL[2] = sm[AP_L + ra + tg + 4]; aL[3] = sm[AP_L + rb + tg + 4];
            const uint32_t vrow = (uint32_t)((kc * 16 + (lid & 15)) * 36) * 4u;
            const uint32_t vh_addr = sb + (uint32_t)AV_H(buf) * 4u + vrow;
            const uint32_t vl_addr = sb + (uint32_t)AV_L(buf) * 4u + vrow;
#pragma unroll
            for (int nt = 0; nt < 8; nt++) {
                uint32_t bH[2], bL[2];
                ldsm_x2_trans(bH[0], bH[1], vh_addr + nt * 16);
                ldsm_x2_trans(bL[0], bL[1], vl_addr + nt * 16);
                mma_bf16(o[nt], aH, bH);
                mma_bf16(o[nt], aL, bH);
                mma_bf16(o[nt], aH, bL);
            }
        }
    }

    // ---- normalize + write merged-head layout ----
    const int b = bh >> 3, h = bh & 7;
    const float inv0 = 1.0f / l0, inv1 = 1.0f / l1;
    const int row0 = q0 + qr + g, row1 = row0 + 8;
#pragma unroll
    for (int nt = 0; nt < 8; nt++) {
        const int col = h * 64 + nt * 8 + tg * 2;
        float2 r0, r1;
        r0.x = o[nt][0] * inv0; r0.y = o[nt][1] * inv0;
        r1.x = o[nt][2] * inv1; r1.y = o[nt][3] * inv1;
        *(float2*)&g_O[(size_t)(b * S_LEN + row0) * D_MODEL + col] = r0;
        *(float2*)&g_O[(size_t)(b * S_LEN + row1) * D_MODEL + col] = r1;
    }
}

// ---------------------------------------------------------------------------
extern "C" void kernel_launch(void* const* d_in, const int* in_sizes, int n_in,
                              void* d_out, int out_size)
{
    const float* q   = (const float*)d_in[0];
    const float* v   = (const float*)d_in[1];
    const float* k   = (const float*)d_in[2];
    const float* w_q = (const float*)d_in[3];
    const float* b_q = (const float*)d_in[4];
    const float* w_k = (const float*)d_in[5];
    const float* b_k = (const float*)d_in[6];
    const float* w_v = (const float*)d_in[7];
    const float* b_v = (const float*)d_in[8];
    const float* w_o = (const float*)d_in[9];
    const float* b_o = (const float*)d_in[10];
    float* out = (float*)d_out;

    const int gemm_smem = 2 * 9216 * 4;     // 73,728 B
    const int attn_smem = 36864 * 4;        // 147,456 B
    cudaFuncSetAttribute(bf16_gemm, cudaFuncAttributeMaxDynamicSharedMemorySize,
                         gemm_smem);
    cudaFuncSetAttribute(attn_mma, cudaFuncAttributeMaxDynamicSharedMemorySize,
                         attn_smem);

    // 1) Q/K/V projections (3xBF16 mma.sync) -> pre-split bf16 hi/lo planes
    bf16_gemm<<<dim3(D_MODEL / 128, MROWS / 128, 3), 256, gemm_smem>>>(
        q, k, v, w_q, b_q, w_k, b_k, w_v, b_v, nullptr, 0);
    // 2) Flash attention (3xBF16 mma.sync, ldmatrix.trans V)
    attn_mma<<<dim3(S_LEN / 128, BHCNT), 256, attn_smem>>>();
    // 3) Output projection (3xBF16 mma.sync)
    bf16_gemm<<<dim3(D_MODEL / 128, MROWS / 128, 1), 256, gemm_smem>>>(
        nullptr, nullptr, nullptr, w_o, b_o, nullptr, nullptr, nullptr, nullptr,
        out, 1);
}

// round 11
// speedup vs baseline: 3.8155x; 1.0050x over previous
#include <cuda_runtime.h>
#include <cuda_bf16.h>
#include <cstdint>

// Problem constants
#define D_MODEL 512
#define S_LEN   2048
#define NB      2
#define NH      8
#define DK      64
#define MROWS   (NB * S_LEN)    // 4096
#define BHCNT   (NB * NH)       // 16
#define PAIRS   (DK / 2)        // 32 u32 per head row
#define DPAIRS  (D_MODEL / 2)   // 256 u32 per full row

// --------------------------------------------------------------------------
// Pre-split bf16 hi/lo planes (pair-packed u32 = [bf16 even | bf16 odd])
// --------------------------------------------------------------------------
__device__ uint32_t g_XAh[3][MROWS * DPAIRS];   // q/k/v activations
__device__ uint32_t g_XAl[3][MROWS * DPAIRS];
__device__ uint32_t g_Wh[4][D_MODEL * DPAIRS];  // w_q w_k w_v w_o
__device__ uint32_t g_Wl[4][D_MODEL * DPAIRS];
__device__ uint32_t g_Oh[MROWS * DPAIRS];       // attention output planes
__device__ uint32_t g_Ol[MROWS * DPAIRS];
// head-split projection outputs
__device__ uint32_t g_Qh[BHCNT * S_LEN * PAIRS];
__device__ uint32_t g_Ql[BHCNT * S_LEN * PAIRS];
__device__ uint32_t g_Kh[BHCNT * S_LEN * PAIRS];
__device__ uint32_t g_Kl[BHCNT * S_LEN * PAIRS];
__device__ uint32_t g_Vh[BHCNT * S_LEN * PAIRS];
__device__ uint32_t g_Vl[BHCNT * S_LEN * PAIRS];

// ===========================================================================
// Helpers (plain sm_75/80 PTX, no 'a'-features)
// ===========================================================================
__device__ __forceinline__ void mma_bf16(float* d, const uint32_t* a, const uint32_t* b)
{
    asm volatile(
        "mma.sync.aligned.m16n8k16.row.col.f32.bf16.bf16.f32 "
        "{%0,%1,%2,%3}, {%4,%5,%6,%7}, {%8,%9}, {%0,%1,%2,%3};"
        : "+f"(d[0]), "+f"(d[1]), "+f"(d[2]), "+f"(d[3])
        : "r"(a[0]), "r"(a[1]), "r"(a[2]), "r"(a[3]), "r"(b[0]), "r"(b[1]));
}

__device__ __forceinline__ void ldsm_x4(uint32_t* r, uint32_t addr)
{
    asm volatile("ldmatrix.sync.aligned.m8n8.x4.shared.b16 {%0,%1,%2,%3}, [%4];"
                 : "=r"(r[0]), "=r"(r[1]), "=r"(r[2]), "=r"(r[3]) : "r"(addr));
}
__device__ __forceinline__ void ldsm_x2(uint32_t& r0, uint32_t& r1, uint32_t addr)
{
    asm volatile("ldmatrix.sync.aligned.m8n8.x2.shared.b16 {%0,%1}, [%2];"
                 : "=r"(r0), "=r"(r1) : "r"(addr));
}
__device__ __forceinline__ void ldsm_x2_trans(uint32_t& r0, uint32_t& r1, uint32_t addr)
{
    asm volatile("ldmatrix.sync.aligned.m8n8.x2.trans.shared.b16 {%0,%1}, [%2];"
                 : "=r"(r0), "=r"(r1) : "r"(addr));
}

__device__ __forceinline__ uint32_t smem_u32(const void* p) {
    uint32_t addr;
    asm("{ .reg .u64 tmp; cvta.to.shared.u64 tmp, %1; cvt.u32.u64 %0, tmp; }"
        : "=r"(addr) : "l"(p));
    return addr;
}

__device__ __forceinline__ void cp_async16(uint32_t dst, const void* src) {
    asm volatile("cp.async.cg.shared.global [%0], [%1], 16;" :: "r"(dst), "l"(src));
}
__device__ __forceinline__ void cp_commit() {
    asm volatile("cp.async.commit_group;" ::: "memory");
}
template <int N>
__device__ __forceinline__ void cp_wait() {
    asm volatile("cp.async.wait_group %0;" :: "n"(N) : "memory");
}

__device__ __forceinline__ void split_bf16x2(float x, float y, uint32_t& h, uint32_t& l)
{
    __nv_bfloat162 hb = __floats2bfloat162_rn(x, y);
    h = *reinterpret_cast<uint32_t*>(&hb);
    float rx = x - __bfloat162float(hb.x);
    float ry = y - __bfloat162float(hb.y);
    __nv_bfloat162 lb = __floats2bfloat162_rn(rx, ry);
    l = *reinterpret_cast<uint32_t*>(&lb);
}

// ===========================================================================
// Pre-split pass: fp32 -> bf16 hi/lo planes. One pair per thread.
// grid (4096, 7): z 0-2 activations (q,k,v), 3-6 weights.
// ===========================================================================
__global__ __launch_bounds__(256) void split_inputs(
    const float* __restrict__ q, const float* __restrict__ k,
    const float* __restrict__ v,
    const float* __restrict__ wq, const float* __restrict__ wk,
    const float* __restrict__ wv, const float* __restrict__ wo)
{
    const int z = blockIdx.y;
    const int idx = blockIdx.x * 256 + threadIdx.x;
    const float* src; uint32_t* dh; uint32_t* dl; int np;
    switch (z) {
        case 0: src = q;  dh = g_XAh[0]; dl = g_XAl[0]; np = MROWS * DPAIRS; break;
        case 1: src = k;  dh = g_XAh[1]; dl = g_XAl[1]; np = MROWS * DPAIRS; break;
        case 2: src = v;  dh = g_XAh[2]; dl = g_XAl[2]; np = MROWS * DPAIRS; break;
        case 3: src = wq; dh = g_Wh[0];  dl = g_Wl[0];  np = D_MODEL * DPAIRS; break;
        case 4: src = wk; dh = g_Wh[1];  dl = g_Wl[1];  np = D_MODEL * DPAIRS; break;
        case 5: src = wv; dh = g_Wh[2];  dl = g_Wl[2];  np = D_MODEL * DPAIRS; break;
        default: src = wo; dh = g_Wh[3]; dl = g_Wl[3];  np = D_MODEL * DPAIRS; break;
    }
    if (idx >= np) return;
    const float2 vv = ((const float2*)src)[idx];
    uint32_t h, l;
    split_bf16x2(vv.x, vv.y, h, l);
    dh[idx] = h; dl[idx] = l;
}

// ===========================================================================
// 3xBF16 GEMM on pre-split planes: out = x @ W^T + bias
//   CTA 128x128, 8 warps (2x4), warp 64x32 (4x4 m16n8k16), k-chunk 32.
//   All fragments via ldmatrix. Rows padded to 20 u32 (80 B): 16B-aligned
//   for cp.async/ldmatrix (72 B in R10 was the misaligned-address bug) and
//   bank-conflict-free (banks 20r mod 32 disjoint over 8 rows).
//   mode 0: z selects Q/K/V proj; epilogue -> head-split hi/lo planes.
//   mode 1: x = g_Oh/g_Ol, W = g_W[3]; fp32 output + bias.
// SMEM: 2 bufs x 4 planes (Ah,Al,Bh,Bl) x [128][20] u32 = 81,920 B
// ===========================================================================
#define GROW  20                    // u32 per smem row
#define GPLN  (128 * GROW)          // 2560 u32 per plane
#define GBUF  (4 * GPLN)            // 10240 u32 per buffer

__global__ __launch_bounds__(256, 1) void bf16_gemm(
    const float* __restrict__ bq_, const float* __restrict__ bk_,
    const float* __restrict__ bv_, float* __restrict__ outp, int mode)
{
    extern __shared__ __align__(16) uint32_t smg[];
    const uint32_t sb = smem_u32(smg);

    const uint32_t *Ah, *Al, *Bh, *Bl;
    const float* bias; float scale = 1.0f;
    uint32_t* dsth = nullptr; uint32_t* dstl = nullptr;
    if (mode == 0) {
        const int z = blockIdx.z;
        Ah = g_XAh[z]; Al = g_XAl[z]; Bh = g_Wh[z]; Bl = g_Wl[z];
        if (z == 0)      { bias = bq_; dsth = g_Qh; dstl = g_Ql; scale = 0.125f; }
        else if (z == 1) { bias = bk_; dsth = g_Kh; dstl = g_Kl; }
        else             { bias = bv_; dsth = g_Vh; dstl = g_Vl; }
    } else {
        Ah = g_Oh; Al = g_Ol; Bh = g_Wh[3]; Bl = g_Wl[3]; bias = bq_;
    }

    const int tid = threadIdx.x;
    const int wid = tid >> 5, lid = tid & 31;
    const int g = lid >> 2, tg = lid & 3;
    const int mwarp = wid & 1, nwarp = wid >> 1;
    const int m0 = blockIdx.y * 128, n0 = blockIdx.x * 128;

    // per-chunk loader: 2048 x 16B (A/B x hi/lo x 128 rows x 4)
    auto load_chunk = [&](int buf, int chunk) {
        const int kcol = chunk * 16;     // u32 column
#pragma unroll
        for (int t = 0; t < 8; t++) {
            const int f = tid + 256 * t;
            const int isB = f >> 10;
            const int rem = f & 1023;
            const int plane = rem >> 9;
            const int r2 = rem & 511;
            const int r = r2 >> 2, cc = r2 & 3;
            const uint32_t* base = isB ? (plane ? Bl : Bh) : (plane ? Al : Ah);
            const uint32_t* src = base + (size_t)((isB ? n0 : m0) + r) * DPAIRS + kcol + cc * 4;
            const uint32_t doff = (uint32_t)(buf * GBUF + (isB * 2 + plane) * GPLN + r * GROW + cc * 4);
            cp_async16(sb + doff * 4u, src);
        }
    };

    float acc[4][4][4];
#pragma unroll
    for (int i = 0; i < 4; i++)
#pragma unroll
        for (int j = 0; j < 4; j++)
#pragma unroll
            for (int e = 0; e < 4; e++) acc[i][j][e] = 0.0f;

    load_chunk(0, 0);
    cp_commit();

    for (int c = 0; c < 16; c++) {
        const int buf = c & 1;
        if (c < 15) {
            load_chunk(buf ^ 1, c + 1);
            cp_commit();
            cp_wait<1>();
        } else {
            cp_wait<0>();
        }
        __syncthreads();

        const uint32_t abase = sb + (uint32_t)(buf * GBUF) * 4u;
#pragma unroll
        for (int ks = 0; ks < 2; ks++) {
            const uint32_t kb = (uint32_t)((lid >> 4) * 16 + ks * 32);
            uint32_t ah[4][4], al[4][4];
#pragma unroll
            for (int i = 0; i < 4; i++) {
                const uint32_t row = (uint32_t)(mwarp * 64 + i * 16 + (lid & 15));
                ldsm_x4(ah[i], abase + row * (GROW * 4) + kb);
                ldsm_x4(al[i], abase + GPLN * 4 + row * (GROW * 4) + kb);
            }
            const uint32_t kbB = (uint32_t)(((lid >> 3) & 1) * 16 + ks * 32);
            uint32_t bh[4][2], bl[4][2];
#pragma unroll
            for (int j = 0; j < 4; j++) {
                const uint32_t row = (uint32_t)(nwarp * 32 + j * 8 + (lid & 7));
                ldsm_x2(bh[j][0], bh[j][1], abase + 2 * GPLN * 4 + row * (GROW * 4) + kbB);
                ldsm_x2(bl[j][0], bl[j][1], abase + 3 * GPLN * 4 + row * (GROW * 4) + kbB);
            }
#pragma unroll
            for (int i = 0; i < 4; i++)
#pragma unroll
                for (int j = 0; j < 4; j++) {
                    mma_bf16(acc[i][j], ah[i], bh[j]);
                    mma_bf16(acc[i][j], al[i], bh[j]);
                    mma_bf16(acc[i][j], ah[i], bl[j]);
                }
        }
        __syncthreads();
    }

    // ---- epilogue ----
#pragma unroll
    for (int j = 0; j < 4; j++) {
        const int n = n0 + nwarp * 32 + j * 8 + 2 * tg;      // even column
        const float bv0 = __ldg(&bias[n]), bv1 = __ldg(&bias[n + 1]);
#pragma unroll
        for (int i = 0; i < 4; i++) {
            const int mA = m0 + mwarp * 64 + i * 16 + g;
            const int mB = mA + 8;
            const float v0 = (acc[i][j][0] + bv0) * scale;
            const float v1 = (acc[i][j][1] + bv1) * scale;
            const float v2 = (acc[i][j][2] + bv0) * scale;
            const float v3 = (acc[i][j][3] + bv1) * scale;
            if (mode == 0) {
                const int h = n >> 6, dkp = (n & 63) >> 1;
                const int bA = mA >> 11, sA = mA & (S_LEN - 1);
                const int bB = mB >> 11, sB = mB & (S_LEN - 1);
                uint32_t hh, ll;
                split_bf16x2(v0, v1, hh, ll);
                const size_t iA = ((size_t)(bA * NH + h) * S_LEN + sA) * PAIRS + dkp;
                dsth[iA] = hh; dstl[iA] = ll;
                split_bf16x2(v2, v3, hh, ll);
                const size_t iB = ((size_t)(bB * NH + h) * S_LEN + sB) * PAIRS + dkp;
                dsth[iB] = hh; dstl[iB] = ll;
            } else {
                *(float2*)&outp[(size_t)mA * D_MODEL + n] = make_float2(v0, v1);
                *(float2*)&outp[(size_t)mB * D_MODEL + n] = make_float2(v2, v3);
            }
        }
    }
}

// ===========================================================================
// 3xBF16 flash attention, pre-split inputs, all-ldmatrix fragments.
//   Per CTA: (bh, 128-q-tile). Warp w owns q-rows w*16..+15. 64-key chunks.
//   Q fragments hoisted to registers; P smem overlays dead Q region.
//   Epilogue writes pre-split O planes for the output projection.
//   Rows padded to 36 u32 (144 B) -> 16B-aligned, conflict-free (verified R9).
//
// SMEM (u32 offsets):
//   Q_H/P_H 0    [128][36]    Q_L/P_L 4608
//   K_H(b) 9216+b*2304  K_L(b) 13824+b*2304
//   V_H(b) 18432+b*2304 V_L(b) 23040+b*2304
// Total 27648 u32 = 110,592 B
// ===========================================================================
#define S_QP_H 0
#define S_QP_L 4608
#define S_K_H(b) (9216  + (b) * 2304)
#define S_K_L(b) (13824 + (b) * 2304)
#define S_V_H(b) (18432 + (b) * 2304)
#define S_V_L(b) (23040 + (b) * 2304)
#define NCHUNK (S_LEN / 64)

__global__ __launch_bounds__(256, 1) void attn_mma()
{
    extern __shared__ __align__(16) uint32_t sm[];
    const uint32_t sb = smem_u32(sm);

    const int tid = threadIdx.x;
    const int wid = tid >> 5, lid = tid & 31;
    const int g = lid >> 2, tg = lid & 3;
    const int bh = blockIdx.y;
    const int q0 = blockIdx.x * 128;
    const int qr = wid * 16;

    const uint32_t* Qh = g_Qh + ((size_t)bh * S_LEN + q0) * PAIRS;
    const uint32_t* Ql = g_Ql + ((size_t)bh * S_LEN + q0) * PAIRS;
    const uint32_t* Kh = g_Kh + (size_t)bh * S_LEN * PAIRS;
    const uint32_t* Kl = g_Kl + (size_t)bh * S_LEN * PAIRS;
    const uint32_t* Vh = g_Vh + (size_t)bh * S_LEN * PAIRS;
    const uint32_t* Vl = g_Vl + (size_t)bh * S_LEN * PAIRS;

    // K/V chunk loader: 4 planes x 64 rows x 8 x 16B
    auto load_kv = [&](int buf, int kt) {
        const size_t base = (size_t)kt * 64 * PAIRS;
#pragma unroll
        for (int t = 0; t < 8; t++) {
            const int f = tid + 256 * t;
            const int plane = f >> 9;
            const int rem = f & 511;
            const int r = rem >> 3, cc = rem & 7;
            const uint32_t* src;
            uint32_t dst;
            const size_t so = base + (size_t)r * PAIRS + cc * 4;
            if (plane == 0)      { src = Kh + so; dst = (uint32_t)S_K_H(buf); }
            else if (plane == 1) { src = Kl + so; dst = (uint32_t)S_K_L(buf); }
            else if (plane == 2) { src = Vh + so; dst = (uint32_t)S_V_H(buf); }
            else                 { src = Vl + so; dst = (uint32_t)S_V_L(buf); }
            cp_async16(sb + (dst + (uint32_t)(r * 36 + cc * 4)) * 4u, src);
        }
    };

    // Prologue: Q (2 planes x 128 rows x 8) + KV chunk 0 in one group
#pragma unroll
    for (int t = 0; t < 8; t++) {
        const int f = tid + 256 * t;
        const int plane = f >> 10;
        const int rem = f & 1023;
        const int r = rem >> 3, cc = rem & 7;
        const uint32_t* src = (plane ? Ql : Qh) + (size_t)r * PAIRS + cc * 4;
        const uint32_t dst = (uint32_t)(plane ? S_QP_L : S_QP_H) + (uint32_t)(r * 36 + cc * 4);
        cp_async16(sb + dst * 4u, src);
    }
    load_kv(0, 0);
    cp_commit();
    cp_wait<0>();
    __syncthreads();

    // Issue chunk-1 prefetch early (targets K/V region, not Q)
    load_kv(1, 1);
    cp_commit();

    // Hoist Q fragments (loop-invariant): 8 ldmatrix.x4 -> 32 regs
    uint32_t qfh[4][4], qfl[4][4];
    {
        const uint32_t rowb = (uint32_t)(qr + (lid & 15)) * 144u + (uint32_t)((lid >> 4) * 16);
#pragma unroll
        for (int kc = 0; kc < 4; kc++) {
            ldsm_x4(qfh[kc], sb + (uint32_t)S_QP_H * 4u + rowb + kc * 32);
            ldsm_x4(qfl[kc], sb + (uint32_t)S_QP_L * 4u + rowb + kc * 32);
        }
    }
    __syncthreads();   // all warps done reading Q smem -> safe to overlay with P

    float m0 = -1e30f, m1 = -1e30f, l0 = 0.0f, l1 = 0.0f;
    float o[8][4];
#pragma unroll
    for (int nt = 0; nt < 8; nt++)
#pragma unroll
        for (int e = 0; e < 4; e++) o[nt][e] = 0.0f;

    for (int kt = 0; kt < NCHUNK; kt++) {
        const int buf = kt & 1;

        // ---- S = Q K^T (3xBF16, K frags via ldmatrix.x2) ----
        float s[8][4];
#pragma unroll
        for (int nt = 0; nt < 8; nt++)
#pragma unroll
            for (int e = 0; e < 4; e++) s[nt][e] = 0.0f;

        const uint32_t kbB = (uint32_t)(((lid >> 3) & 1) * 16);
        const uint32_t khb = sb + (uint32_t)S_K_H(buf) * 4u + kbB;
        const uint32_t klb = sb + (uint32_t)S_K_L(buf) * 4u + kbB;
#pragma unroll
        for (int kc = 0; kc < 4; kc++) {
#pragma unroll
            for (int nt = 0; nt < 8; nt++) {
                const uint32_t roff = (uint32_t)(nt * 8 + (lid & 7)) * 144u + kc * 32;
                uint32_t bH[2], bL[2];
                ldsm_x2(bH[0], bH[1], khb + roff);
                ldsm_x2(bL[0], bL[1], klb + roff);
                mma_bf16(s[nt], qfh[kc], bH);
                mma_bf16(s[nt], qfl[kc], bH);
                mma_bf16(s[nt], qfh[kc], bL);
            }
        }

        // ---- online softmax ----
        {
            float mx0 = -1e30f, mx1 = -1e30f;
#pragma unroll
            for (int nt = 0; nt < 8; nt++) {
                mx0 = fmaxf(mx0, fmaxf(s[nt][0], s[nt][1]));
                mx1 = fmaxf(mx1, fmaxf(s[nt][2], s[nt][3]));
            }
            mx0 = fmaxf(mx0, __shfl_xor_sync(0xffffffffu, mx0, 1));
            mx0 = fmaxf(mx0, __shfl_xor_sync(0xffffffffu, mx0, 2));
            mx1 = fmaxf(mx1, __shfl_xor_sync(0xffffffffu, mx1, 1));
            mx1 = fmaxf(mx1, __shfl_xor_sync(0xffffffffu, mx1, 2));
            const float nm0 = fmaxf(m0, mx0), nm1 = fmaxf(m1, mx1);
            const float al0 = __expf(m0 - nm0), al1 = __expf(m1 - nm1);
            m0 = nm0; m1 = nm1;
            float sum0 = 0.0f, sum1 = 0.0f;
#pragma unroll
            for (int nt = 0; nt < 8; nt++) {
                s[nt][0] = __expf(s[nt][0] - nm0);
                s[nt][1] = __expf(s[nt][1] - nm0);
                s[nt][2] = __expf(s[nt][2] - nm1);
                s[nt][3] = __expf(s[nt][3] - nm1);
                sum0 += s[nt][0] + s[nt][1];
                sum1 += s[nt][2] + s[nt][3];
            }
            sum0 += __shfl_xor_sync(0xffffffffu, sum0, 1);
            sum0 += __shfl_xor_sync(0xffffffffu, sum0, 2);
            sum1 += __shfl_xor_sync(0xffffffffu, sum1, 1);
            sum1 += __shfl_xor_sync(0xffffffffu, sum1, 2);
            l0 = l0 * al0 + sum0;
            l1 = l1 * al1 + sum1;
#pragma unroll
            for (int nt = 0; nt < 8; nt++) {
                o[nt][0] *= al0; o[nt][1] *= al0;
                o[nt][2] *= al1; o[nt][3] *= al1;
            }
        }

        // ---- stage P (hi/lo), warp-local rows (overlays Q region) ----
#pragma unroll
        for (int nt = 0; nt < 8; nt++) {
            uint32_t h0, lo0, h1, lo1;
            split_bf16x2(s[nt][0], s[nt][1], h0, lo0);
            split_bf16x2(s[nt][2], s[nt][3], h1, lo1);
            const int kp = nt * 4 + tg;
            sm[S_QP_H + (qr + g) * 36 + kp]     = h0;
            sm[S_QP_L + (qr + g) * 36 + kp]     = lo0;
            sm[S_QP_H + (qr + g + 8) * 36 + kp] = h1;
            sm[S_QP_L + (qr + g + 8) * 36 + kp] = lo1;
        }
        __syncwarp();

        // ---- O += P V (P frags ldmatrix.x4, V frags ldmatrix.x2.trans) ----
        const uint32_t prow = (uint32_t)(qr + (lid & 15)) * 144u + (uint32_t)((lid >> 4) * 16);
        const uint32_t vb_h = sb + (uint32_t)S_V_H(buf) * 4u;
        const uint32_t vb_l = sb + (uint32_t)S_V_L(buf) * 4u;
#pragma unroll
        for (int kc = 0; kc < 4; kc++) {
            uint32_t paH[4], paL[4];
            ldsm_x4(paH, sb + (uint32_t)S_QP_H * 4u + prow + kc * 32);
            ldsm_x4(paL, sb + (uint32_t)S_QP_L * 4u + prow + kc * 32);
            const uint32_t vrow = (uint32_t)(kc * 16 + (lid & 15)) * 144u;
#pragma unroll
            for (int nt = 0; nt < 8; nt++) {
                uint32_t bH[2], bL[2];
                ldsm_x2_trans(bH[0], bH[1], vb_h + vrow + nt * 16);
                ldsm_x2_trans(bL[0], bL[1], vb_l + vrow + nt * 16);
                mma_bf16(o[nt], paH, bH);
                mma_bf16(o[nt], paL, bH);
                mma_bf16(o[nt], paH, bL);
            }
        }

        // ---- pipeline tail: complete prefetch kt+1, recycle buf for kt+2 ----
        if (kt + 1 < NCHUNK) {
            cp_wait<0>();
            __syncthreads();
            if (kt + 2 < NCHUNK) {
                load_kv(buf, kt + 2);
                cp_commit();
            }
        }
    }

    // ---- normalize + write pre-split merged-head O planes ----
    const int b = bh >> 3, h = bh & 7;
    const float inv0 = 1.0f / l0, inv1 = 1.0f / l1;
    const int row0 = q0 + qr + g, row1 = row0 + 8;
#pragma unroll
    for (int nt = 0; nt < 8; nt++) {
        const int cp = h * 32 + nt * 4 + tg;     // u32 pair column
        uint32_t hh, ll;
        split_bf16x2(o[nt][0] * inv0, o[nt][1] * inv0, hh, ll);
        g_Oh[(size_t)(b * S_LEN + row0) * DPAIRS + cp] = hh;
        g_Ol[(size_t)(b * S_LEN + row0) * DPAIRS + cp] = ll;
        split_bf16x2(o[nt][2] * inv1, o[nt][3] * inv1, hh, ll);
        g_Oh[(size_t)(b * S_LEN + row1) * DPAIRS + cp] = hh;
        g_Ol[(size_t)(b * S_LEN + row1) * DPAIRS + cp] = ll;
    }
}

// ---------------------------------------------------------------------------
extern "C" void kernel_launch(void* const* d_in, const int* in_sizes, int n_in,
                              void* d_out, int out_size)
{
    const float* q   = (const float*)d_in[0];
    const float* v   = (const float*)d_in[1];
    const float* k   = (const float*)d_in[2];
    const float* w_q = (const float*)d_in[3];
    const float* b_q = (const float*)d_in[4];
    const float* w_k = (const float*)d_in[5];
    const float* b_k = (const float*)d_in[6];
    const float* w_v = (const float*)d_in[7];
    const float* b_v = (const float*)d_in[8];
    const float* w_o = (const float*)d_in[9];
    const float* b_o = (const float*)d_in[10];
    float* out = (float*)d_out;

    const int gemm_smem = 2 * GBUF * 4;   // 81,920 B
    const int attn_smem = 27648 * 4;      // 110,592 B
    cudaFuncSetAttribute(bf16_gemm, cudaFuncAttributeMaxDynamicSharedMemorySize,
                         gemm_smem);
    cudaFuncSetAttribute(attn_mma, cudaFuncAttributeMaxDynamicSharedMemorySize,
                         attn_smem);

    // 0) Pre-split all inputs to bf16 hi/lo planes
    split_inputs<<<dim3(MROWS * DPAIRS / 256, 7), 256>>>(q, k, v, w_q, w_k, w_v, w_o);
    // 1) Q/K/V projections (3xBF16, all-ldmatrix) -> head-split planes
    bf16_gemm<<<dim3(D_MODEL / 128, MROWS / 128, 3), 256, gemm_smem>>>(
        b_q, b_k, b_v, nullptr, 0);
    // 2) Flash attention (3xBF16, Q hoisted, all-ldmatrix) -> O planes
    attn_mma<<<dim3(S_LEN / 128, BHCNT), 256, attn_smem>>>();
    // 3) Output projection (3xBF16) -> fp32 d_out
    bf16_gemm<<<dim3(D_MODEL / 128, MROWS / 128, 1), 256, gemm_smem>>>(
        b_o, nullptr, nullptr, out, 1);
}

// round 12
// speedup vs baseline: 4.1201x; 1.0798x over previous
#include <cuda_runtime.h>
#include <cuda_bf16.h>
#include <cstdint>

// Problem constants
#define D_MODEL 512
#define S_LEN   2048
#define NB      2
#define NH      8
#define DK      64
#define MROWS   (NB * S_LEN)    // 4096
#define BHCNT   (NB * NH)       // 16
#define PAIRS   (DK / 2)        // 32 u32 per head row
#define DPAIRS  (D_MODEL / 2)   // 256 u32 per full row

// --------------------------------------------------------------------------
// Pre-split bf16 hi/lo planes (pair-packed u32 = [bf16 even | bf16 odd])
// --------------------------------------------------------------------------
__device__ uint32_t g_XAh[3][MROWS * DPAIRS];   // q/k/v activations
__device__ uint32_t g_XAl[3][MROWS * DPAIRS];
__device__ uint32_t g_Wh[4][D_MODEL * DPAIRS];  // w_q w_k w_v w_o
__device__ uint32_t g_Wl[4][D_MODEL * DPAIRS];
__device__ uint32_t g_Oh[MROWS * DPAIRS];       // attention output planes
__device__ uint32_t g_Ol[MROWS * DPAIRS];
// head-split projection outputs
__device__ uint32_t g_Qh[BHCNT * S_LEN * PAIRS];
__device__ uint32_t g_Ql[BHCNT * S_LEN * PAIRS];
__device__ uint32_t g_Kh[BHCNT * S_LEN * PAIRS];
__device__ uint32_t g_Kl[BHCNT * S_LEN * PAIRS];
__device__ uint32_t g_Vh[BHCNT * S_LEN * PAIRS];
__device__ uint32_t g_Vl[BHCNT * S_LEN * PAIRS];

// ===========================================================================
// Helpers (plain sm_75/80 PTX, no 'a'-features)
// ===========================================================================
__device__ __forceinline__ void mma_bf16(float* d, const uint32_t* a, const uint32_t* b)
{
    asm volatile(
        "mma.sync.aligned.m16n8k16.row.col.f32.bf16.bf16.f32 "
        "{%0,%1,%2,%3}, {%4,%5,%6,%7}, {%8,%9}, {%0,%1,%2,%3};"
        : "+f"(d[0]), "+f"(d[1]), "+f"(d[2]), "+f"(d[3])
        : "r"(a[0]), "r"(a[1]), "r"(a[2]), "r"(a[3]), "r"(b[0]), "r"(b[1]));
}

__device__ __forceinline__ void ldsm_x4(uint32_t* r, uint32_t addr)
{
    asm volatile("ldmatrix.sync.aligned.m8n8.x4.shared.b16 {%0,%1,%2,%3}, [%4];"
                 : "=r"(r[0]), "=r"(r[1]), "=r"(r[2]), "=r"(r[3]) : "r"(addr));
}
__device__ __forceinline__ void ldsm_x4_trans(uint32_t* r, uint32_t addr)
{
    asm volatile("ldmatrix.sync.aligned.m8n8.x4.trans.shared.b16 {%0,%1,%2,%3}, [%4];"
                 : "=r"(r[0]), "=r"(r[1]), "=r"(r[2]), "=r"(r[3]) : "r"(addr));
}

__device__ __forceinline__ uint32_t smem_u32(const void* p) {
    uint32_t addr;
    asm("{ .reg .u64 tmp; cvta.to.shared.u64 tmp, %1; cvt.u32.u64 %0, tmp; }"
        : "=r"(addr) : "l"(p));
    return addr;
}

__device__ __forceinline__ void cp_async16(uint32_t dst, const void* src) {
    asm volatile("cp.async.cg.shared.global [%0], [%1], 16;" :: "r"(dst), "l"(src));
}
__device__ __forceinline__ void cp_commit() {
    asm volatile("cp.async.commit_group;" ::: "memory");
}
template <int N>
__device__ __forceinline__ void cp_wait() {
    asm volatile("cp.async.wait_group %0;" :: "n"(N) : "memory");
}

__device__ __forceinline__ void split_bf16x2(float x, float y, uint32_t& h, uint32_t& l)
{
    __nv_bfloat162 hb = __floats2bfloat162_rn(x, y);
    h = *reinterpret_cast<uint32_t*>(&hb);
    float rx = x - __bfloat162float(hb.x);
    float ry = y - __bfloat162float(hb.y);
    __nv_bfloat162 lb = __floats2bfloat162_rn(rx, ry);
    l = *reinterpret_cast<uint32_t*>(&lb);
}

// ===========================================================================
// Pre-split pass: fp32 -> bf16 hi/lo planes. One pair per thread.
// ===========================================================================
__global__ __launch_bounds__(256) void split_inputs(
    const float* __restrict__ q, const float* __restrict__ k,
    const float* __restrict__ v,
    const float* __restrict__ wq, const float* __restrict__ wk,
    const float* __restrict__ wv, const float* __restrict__ wo)
{
    const int z = blockIdx.y;
    const int idx = blockIdx.x * 256 + threadIdx.x;
    const float* src; uint32_t* dh; uint32_t* dl; int np;
    switch (z) {
        case 0: src = q;  dh = g_XAh[0]; dl = g_XAl[0]; np = MROWS * DPAIRS; break;
        case 1: src = k;  dh = g_XAh[1]; dl = g_XAl[1]; np = MROWS * DPAIRS; break;
        case 2: src = v;  dh = g_XAh[2]; dl = g_XAl[2]; np = MROWS * DPAIRS; break;
        case 3: src = wq; dh = g_Wh[0];  dl = g_Wl[0];  np = D_MODEL * DPAIRS; break;
        case 4: src = wk; dh = g_Wh[1];  dl = g_Wl[1];  np = D_MODEL * DPAIRS; break;
        case 5: src = wv; dh = g_Wh[2];  dl = g_Wl[2];  np = D_MODEL * DPAIRS; break;
        default: src = wo; dh = g_Wh[3]; dl = g_Wl[3];  np = D_MODEL * DPAIRS; break;
    }
    if (idx >= np) return;
    const float2 vv = ((const float2*)src)[idx];
    uint32_t h, l;
    split_bf16x2(vv.x, vv.y, h, l);
    dh[idx] = h; dl[idx] = l;
}

// ===========================================================================
// 3xBF16 GEMM, 512 threads: CTA 128x128, 16 warps (4m x 4n), warp 32x32.
//   k-chunk 32 (2 k16 steps). A-frags ldmatrix.x4; B-frags x4 over j-pairs.
//   Rows padded to 20 u32 (80 B, 16B-aligned, bank-conflict-free).
// SMEM: 2 bufs x 4 planes x [128][20] u32 = 81,920 B
// ===========================================================================
#define GROW  20
#define GPLN  (128 * GROW)          // 2560 u32 per plane
#define GBUF  (4 * GPLN)            // 10240 u32 per buffer

__global__ __launch_bounds__(512, 1) void bf16_gemm(
    const float* __restrict__ bq_, const float* __restrict__ bk_,
    const float* __restrict__ bv_, float* __restrict__ outp, int mode)
{
    extern __shared__ __align__(16) uint32_t smg[];
    const uint32_t sb = smem_u32(smg);

    const uint32_t *Ah, *Al, *Bh, *Bl;
    const float* bias; float scale = 1.0f;
    uint32_t* dsth = nullptr; uint32_t* dstl = nullptr;
    if (mode == 0) {
        const int z = blockIdx.z;
        Ah = g_XAh[z]; Al = g_XAl[z]; Bh = g_Wh[z]; Bl = g_Wl[z];
        if (z == 0)      { bias = bq_; dsth = g_Qh; dstl = g_Ql; scale = 0.125f; }
        else if (z == 1) { bias = bk_; dsth = g_Kh; dstl = g_Kl; }
        else             { bias = bv_; dsth = g_Vh; dstl = g_Vl; }
    } else {
        Ah = g_Oh; Al = g_Ol; Bh = g_Wh[3]; Bl = g_Wl[3]; bias = bq_;
    }

    const int tid = threadIdx.x;
    const int wid = tid >> 5, lid = tid & 31;
    const int g = lid >> 2, tg = lid & 3;
    const int mwarp = wid & 3, nwarp = wid >> 2;     // 4 x 4 warp grid
    const int m0 = blockIdx.y * 128, n0 = blockIdx.x * 128;

    // per-chunk loader: 2048 x 16B (A/B x hi/lo x 128 rows x 4), 4 per thread
    auto load_chunk = [&](int buf, int chunk) {
        const int kcol = chunk * 16;
#pragma unroll
        for (int t = 0; t < 4; t++) {
            const int f = tid + 512 * t;
            const int isB = f >> 10;
            const int rem = f & 1023;
            const int plane = rem >> 9;
            const int r2 = rem & 511;
            const int r = r2 >> 2, cc = r2 & 3;
            const uint32_t* base = isB ? (plane ? Bl : Bh) : (plane ? Al : Ah);
            const uint32_t* src = base + (size_t)((isB ? n0 : m0) + r) * DPAIRS + kcol + cc * 4;
            const uint32_t doff = (uint32_t)(buf * GBUF + (isB * 2 + plane) * GPLN + r * GROW + cc * 4);
            cp_async16(sb + doff * 4u, src);
        }
    };

    float acc[2][4][4];
#pragma unroll
    for (int i = 0; i < 2; i++)
#pragma unroll
        for (int j = 0; j < 4; j++)
#pragma unroll
            for (int e = 0; e < 4; e++) acc[i][j][e] = 0.0f;

    load_chunk(0, 0);
    cp_commit();

    for (int c = 0; c < 16; c++) {
        const int buf = c & 1;
        if (c < 15) {
            load_chunk(buf ^ 1, c + 1);
            cp_commit();
            cp_wait<1>();
        } else {
            cp_wait<0>();
        }
        __syncthreads();

        const uint32_t abase = sb + (uint32_t)(buf * GBUF) * 4u;
#pragma unroll
        for (int ks = 0; ks < 2; ks++) {
            // A fragments: 2 m-tiles x 2 planes, ldmatrix.x4
            const uint32_t kb = (uint32_t)((lid >> 4) * 16 + ks * 32);
            uint32_t ah[2][4], al[2][4];
#pragma unroll
            for (int i = 0; i < 2; i++) {
                const uint32_t row = (uint32_t)(mwarp * 32 + i * 16 + (lid & 15));
                ldsm_x4(ah[i], abase + row * (GROW * 4) + kb);
                ldsm_x4(al[i], abase + GPLN * 4 + row * (GROW * 4) + kb);
            }
            // B fragments: x4 over j-pairs (lanes 16-31 -> second j tile)
            uint32_t bh[4][2], bl[4][2];
            const uint32_t kbB = (uint32_t)(((lid >> 3) & 1) * 16 + ks * 32);
#pragma unroll
            for (int jp = 0; jp < 2; jp++) {
                const uint32_t row = (uint32_t)(nwarp * 32 + jp * 16 + ((lid >> 4) & 1) * 8 + (lid & 7));
                uint32_t r4[4];
                ldsm_x4(r4, abase + 2 * GPLN * 4 + row * (GROW * 4) + kbB);
                bh[jp * 2][0] = r4[0]; bh[jp * 2][1] = r4[1];
                bh[jp * 2 + 1][0] = r4[2]; bh[jp * 2 + 1][1] = r4[3];
                ldsm_x4(r4, abase + 3 * GPLN * 4 + row * (GROW * 4) + kbB);
                bl[jp * 2][0] = r4[0]; bl[jp * 2][1] = r4[1];
                bl[jp * 2 + 1][0] = r4[2]; bl[jp * 2 + 1][1] = r4[3];
            }
#pragma unroll
            for (int i = 0; i < 2; i++)
#pragma unroll
                for (int j = 0; j < 4; j++) {
                    mma_bf16(acc[i][j], ah[i], bh[j]);
                    mma_bf16(acc[i][j], al[i], bh[j]);
                    mma_bf16(acc[i][j], ah[i], bl[j]);
                }
        }
        __syncthreads();
    }

    // ---- epilogue ----
#pragma unroll
    for (int j = 0; j < 4; j++) {
        const int n = n0 + nwarp * 32 + j * 8 + 2 * tg;      // even column
        const float bv0 = __ldg(&bias[n]), bv1 = __ldg(&bias[n + 1]);
#pragma unroll
        for (int i = 0; i < 2; i++) {
            const int mA = m0 + mwarp * 32 + i * 16 + g;
            const int mB = mA + 8;
            const float v0 = (acc[i][j][0] + bv0) * scale;
            const float v1 = (acc[i][j][1] + bv1) * scale;
            const float v2 = (acc[i][j][2] + bv0) * scale;
            const float v3 = (acc[i][j][3] + bv1) * scale;
            if (mode == 0) {
                const int h = n >> 6, dkp = (n & 63) >> 1;
                const int bA = mA >> 11, sA = mA & (S_LEN - 1);
                const int bB = mB >> 11, sB = mB & (S_LEN - 1);
                uint32_t hh, ll;
                split_bf16x2(v0, v1, hh, ll);
                const size_t iA = ((size_t)(bA * NH + h) * S_LEN + sA) * PAIRS + dkp;
                dsth[iA] = hh; dstl[iA] = ll;
                split_bf16x2(v2, v3, hh, ll);
                const size_t iB = ((size_t)(bB * NH + h) * S_LEN + sB) * PAIRS + dkp;
                dsth[iB] = hh; dstl[iB] = ll;
            } else {
                *(float2*)&outp[(size_t)mA * D_MODEL + n] = make_float2(v0, v1);
                *(float2*)&outp[(size_t)mB * D_MODEL + n] = make_float2(v2, v3);
            }
        }
    }
}

// ===========================================================================
// 3xBF16 flash attention, 512 threads: 256-row q-tile, 16 warps x 16 rows.
//   64-key chunks, double-buffered cp.async. Q persistent in smem (re-loaded
//   per chunk via ldmatrix.x4); K-frags x4 over nt-pairs; V-frags x4.trans
//   over d-group pairs; P in its own smem region (warp-local, __syncwarp).
//
// SMEM (u32 offsets, rows 36 u32 = 144 B):
//   Q_H 0 [256][36]  Q_L 9216   P_H 18432 [256][36]  P_L 27648
//   K_H(b) 36864+b*2304  K_L(b) 41472+b*2304
//   V_H(b) 46080+b*2304  V_L(b) 50688+b*2304
// Total 55296 u32 = 221,184 B
// ===========================================================================
#define S_Q_H 0
#define S_Q_L 9216
#define S_P_H 18432
#define S_P_L 27648
#define S_K_H(b) (36864 + (b) * 2304)
#define S_K_L(b) (41472 + (b) * 2304)
#define S_V_H(b) (46080 + (b) * 2304)
#define S_V_L(b) (50688 + (b) * 2304)
#define NCHUNK (S_LEN / 64)
#define QTILE  256

__global__ __launch_bounds__(512, 1) void attn_mma()
{
    extern __shared__ __align__(16) uint32_t sm[];
    const uint32_t sb = smem_u32(sm);

    const int tid = threadIdx.x;
    const int wid = tid >> 5, lid = tid & 31;
    const int g = lid >> 2, tg = lid & 3;
    const int bh = blockIdx.y;
    const int q0 = blockIdx.x * QTILE;
    const int qr = wid * 16;

    const uint32_t* Qh = g_Qh + ((size_t)bh * S_LEN + q0) * PAIRS;
    const uint32_t* Ql = g_Ql + ((size_t)bh * S_LEN + q0) * PAIRS;
    const uint32_t* Kh = g_Kh + (size_t)bh * S_LEN * PAIRS;
    const uint32_t* Kl = g_Kl + (size_t)bh * S_LEN * PAIRS;
    const uint32_t* Vh = g_Vh + (size_t)bh * S_LEN * PAIRS;
    const uint32_t* Vl = g_Vl + (size_t)bh * S_LEN * PAIRS;

    // K/V chunk loader: 4 planes x 64 rows x 8 x 16B = 2048, 4 per thread
    auto load_kv = [&](int buf, int kt) {
        const size_t base = (size_t)kt * 64 * PAIRS;
#pragma unroll
        for (int t = 0; t < 4; t++) {
            const int f = tid + 512 * t;
            const int plane = f >> 9;
            const int rem = f & 511;
            const int r = rem >> 3, cc = rem & 7;
            const uint32_t* src;
            uint32_t dst;
            const size_t so = base + (size_t)r * PAIRS + cc * 4;
            if (plane == 0)      { src = Kh + so; dst = (uint32_t)S_K_H(buf); }
            else if (plane == 1) { src = Kl + so; dst = (uint32_t)S_K_L(buf); }
            else if (plane == 2) { src = Vh + so; dst = (uint32_t)S_V_H(buf); }
            else                 { src = Vl + so; dst = (uint32_t)S_V_L(buf); }
            cp_async16(sb + (dst + (uint32_t)(r * 36 + cc * 4)) * 4u, src);
        }
    };

    // Prologue: Q (2 planes x 256 rows x 8 = 4096 chunks) + KV chunk 0
#pragma unroll
    for (int t = 0; t < 8; t++) {
        const int f = tid + 512 * t;
        const int plane = f >> 11;
        const int rem = f & 2047;
        const int r = rem >> 3, cc = rem & 7;
        const uint32_t* src = (plane ? Ql : Qh) + (size_t)r * PAIRS + cc * 4;
        const uint32_t dst = (uint32_t)(plane ? S_Q_L : S_Q_H) + (uint32_t)(r * 36 + cc * 4);
        cp_async16(sb + dst * 4u, src);
    }
    load_kv(0, 0);
    cp_commit();
    cp_wait<0>();
    __syncthreads();

    // Prefetch chunk 1
    load_kv(1, 1);
    cp_commit();

    float m0 = -1e30f, m1 = -1e30f, l0 = 0.0f, l1 = 0.0f;
    float o[8][4];
#pragma unroll
    for (int nt = 0; nt < 8; nt++)
#pragma unroll
        for (int e = 0; e < 4; e++) o[nt][e] = 0.0f;

    const uint32_t qrowb = (uint32_t)(qr + (lid & 15)) * 144u + (uint32_t)((lid >> 4) * 16);

    for (int kt = 0; kt < NCHUNK; kt++) {
        const int buf = kt & 1;

        // ---- S = Q K^T (A-frags x4 from smem; K-frags x4 over nt-pairs) ----
        float s[8][4];
#pragma unroll
        for (int nt = 0; nt < 8; nt++)
#pragma unroll
            for (int e = 0; e < 4; e++) s[nt][e] = 0.0f;

        const uint32_t khb = sb + (uint32_t)S_K_H(buf) * 4u;
        const uint32_t klb = sb + (uint32_t)S_K_L(buf) * 4u;
        const uint32_t kroff = (uint32_t)(((lid >> 4) & 1) * 8 + (lid & 7)) * 144u
                             + (uint32_t)(((lid >> 3) & 1) * 16);
#pragma unroll
        for (int kc = 0; kc < 4; kc++) {
            uint32_t aH[4], aL[4];
            ldsm_x4(aH, sb + (uint32_t)S_Q_H * 4u + qrowb + kc * 32);
            ldsm_x4(aL, sb + (uint32_t)S_Q_L * 4u + qrowb + kc * 32);
#pragma unroll
            for (int ntp = 0; ntp < 4; ntp++) {
                const uint32_t ro = (uint32_t)(ntp * 16) * 144u + kroff + kc * 32;
                uint32_t rH[4], rL[4];
                ldsm_x4(rH, khb + ro);
                ldsm_x4(rL, klb + ro);
                mma_bf16(s[ntp * 2],     aH, &rH[0]);
                mma_bf16(s[ntp * 2],     aL, &rH[0]);
                mma_bf16(s[ntp * 2],     aH, &rL[0]);
                mma_bf16(s[ntp * 2 + 1], aH, &rH[2]);
                mma_bf16(s[ntp * 2 + 1], aL, &rH[2]);
                mma_bf16(s[ntp * 2 + 1], aH, &rL[2]);
            }
        }

        // ---- online softmax ----
        {
            float mx0 = -1e30f, mx1 = -1e30f;
#pragma unroll
            for (int nt = 0; nt < 8; nt++) {
                mx0 = fmaxf(mx0, fmaxf(s[nt][0], s[nt][1]));
                mx1 = fmaxf(mx1, fmaxf(s[nt][2], s[nt][3]));
            }
            mx0 = fmaxf(mx0, __shfl_xor_sync(0xffffffffu, mx0, 1));
            mx0 = fmaxf(mx0, __shfl_xor_sync(0xffffffffu, mx0, 2));
            mx1 = fmaxf(mx1, __shfl_xor_sync(0xffffffffu, mx1, 1));
            mx1 = fmaxf(mx1, __shfl_xor_sync(0xffffffffu, mx1, 2));
            const float nm0 = fmaxf(m0, mx0), nm1 = fmaxf(m1, mx1);
            const float al0 = __expf(m0 - nm0), al1 = __expf(m1 - nm1);
            m0 = nm0; m1 = nm1;
            float sum0 = 0.0f, sum1 = 0.0f;
#pragma unroll
            for (int nt = 0; nt < 8; nt++) {
                s[nt][0] = __expf(s[nt][0] - nm0);
                s[nt][1] = __expf(s[nt][1] - nm0);
                s[nt][2] = __expf(s[nt][2] - nm1);
                s[nt][3] = __expf(s[nt][3] - nm1);
                sum0 += s[nt][0] + s[nt][1];
                sum1 += s[nt][2] + s[nt][3];
            }
            sum0 += __shfl_xor_sync(0xffffffffu, sum0, 1);
            sum0 += __shfl_xor_sync(0xffffffffu, sum0, 2);
            sum1 += __shfl_xor_sync(0xffffffffu, sum1, 1);
            sum1 += __shfl_xor_sync(0xffffffffu, sum1, 2);
            l0 = l0 * al0 + sum0;
            l1 = l1 * al1 + sum1;
#pragma unroll
            for (int nt = 0; nt < 8; nt++) {
                o[nt][0] *= al0; o[nt][1] *= al0;
                o[nt][2] *= al1; o[nt][3] *= al1;
            }
        }

        // ---- stage P (hi/lo), warp-local rows ----
#pragma unroll
        for (int nt = 0; nt < 8; nt++) {
            uint32_t h0, lo0, h1, lo1;
            split_bf16x2(s[nt][0], s[nt][1], h0, lo0);
            split_bf16x2(s[nt][2], s[nt][3], h1, lo1);
            const int kp = nt * 4 + tg;
            sm[S_P_H + (qr + g) * 36 + kp]     = h0;
            sm[S_P_L + (qr + g) * 36 + kp]     = lo0;
            sm[S_P_H + (qr + g + 8) * 36 + kp] = h1;
            sm[S_P_L + (qr + g + 8) * 36 + kp] = lo1;
        }
        __syncwarp();

        // ---- O += P V (P x4; V x4.trans over d-group pairs) ----
        const uint32_t prowb = (uint32_t)(qr + (lid & 15)) * 144u + (uint32_t)((lid >> 4) * 16);
        const uint32_t vb_h = sb + (uint32_t)S_V_H(buf) * 4u;
        const uint32_t vb_l = sb + (uint32_t)S_V_L(buf) * 4u;
#pragma unroll
        for (int kc = 0; kc < 4; kc++) {
            uint32_t paH[4], paL[4];
            ldsm_x4(paH, sb + (uint32_t)S_P_H * 4u + prowb + kc * 32);
            ldsm_x4(paL, sb + (uint32_t)S_P_L * 4u + prowb + kc * 32);
            const uint32_t vrow = (uint32_t)(kc * 16 + (lid & 15)) * 144u
                                + (uint32_t)((lid >> 4) * 16);
#pragma unroll
            for (int ntp = 0; ntp < 4; ntp++) {
                uint32_t rH[4], rL[4];
                ldsm_x4_trans(rH, vb_h + vrow + ntp * 32);
                ldsm_x4_trans(rL, vb_l + vrow + ntp * 32);
                mma_bf16(o[ntp * 2],     paH, &rH[0]);
                mma_bf16(o[ntp * 2],     paL, &rH[0]);
                mma_bf16(o[ntp * 2],     paH, &rL[0]);
                mma_bf16(o[ntp * 2 + 1], paH, &rH[2]);
                mma_bf16(o[ntp * 2 + 1], paL, &rH[2]);
                mma_bf16(o[ntp * 2 + 1], paH, &rL[2]);
            }
        }

        // ---- pipeline tail ----
        if (kt + 1 < NCHUNK) {
            cp_wait<0>();
            __syncthreads();
            if (kt + 2 < NCHUNK) {
                load_kv(buf, kt + 2);
                cp_commit();
            }
        }
    }

    // ---- normalize + write pre-split merged-head O planes ----
    const int b = bh >> 3, h = bh & 7;
    const float inv0 = 1.0f / l0, inv1 = 1.0f / l1;
    const int row0 = q0 + qr + g, row1 = row0 + 8;
#pragma unroll
    for (int nt = 0; nt < 8; nt++) {
        const int cp = h * 32 + nt * 4 + tg;
        uint32_t hh, ll;
        split_bf16x2(o[nt][0] * inv0, o[nt][1] * inv0, hh, ll);
        g_Oh[(size_t)(b * S_LEN + row0) * DPAIRS + cp] = hh;
        g_Ol[(size_t)(b * S_LEN + row0) * DPAIRS + cp] = ll;
        split_bf16x2(o[nt][2] * inv1, o[nt][3] * inv1, hh, ll);
        g_Oh[(size_t)(b * S_LEN + row1) * DPAIRS + cp] = hh;
        g_Ol[(size_t)(b * S_LEN + row1) * DPAIRS + cp] = ll;
    }
}

// ---------------------------------------------------------------------------
extern "C" void kernel_launch(void* const* d_in, const int* in_sizes, int n_in,
                              void* d_out, int out_size)
{
    const float* q   = (const float*)d_in[0];
    const float* v   = (const float*)d_in[1];
    const float* k   = (const float*)d_in[2];
    const float* w_q = (const float*)d_in[3];
    const float* b_q = (const float*)d_in[4];
    const float* w_k = (const float*)d_in[5];
    const float* b_k = (const float*)d_in[6];
    const float* w_v = (const float*)d_in[7];
    const float* b_v = (const float*)d_in[8];
    const float* w_o = (const float*)d_in[9];
    const float* b_o = (const float*)d_in[10];
    float* out = (float*)d_out;

    const int gemm_smem = 2 * GBUF * 4;   // 81,920 B
    const int attn_smem = 55296 * 4;      // 221,184 B
    cudaFuncSetAttribute(bf16_gemm, cudaFuncAttributeMaxDynamicSharedMemorySize,
                         gemm_smem);
    cudaFuncSetAttribute(attn_mma, cudaFuncAttributeMaxDynamicSharedMemorySize,
                         attn_smem);

    // 0) Pre-split all inputs to bf16 hi/lo planes
    split_inputs<<<dim3(MROWS * DPAIRS / 256, 7), 256>>>(q, k, v, w_q, w_k, w_v, w_o);
    // 1) Q/K/V projections (3xBF16, 512 threads)
    bf16_gemm<<<dim3(D_MODEL / 128, MROWS / 128, 3), 512, gemm_smem>>>(
        b_q, b_k, b_v, nullptr, 0);
    // 2) Flash attention (3xBF16, 512 threads, 256-row q-tiles)
    attn_mma<<<dim3(S_LEN / QTILE, BHCNT), 512, attn_smem>>>();
    // 3) Output projection (3xBF16) -> fp32 d_out
    bf16_gemm<<<dim3(D_MODEL / 128, MROWS / 128, 1), 512, gemm_smem>>>(
        b_o, nullptr, nullptr, out, 1);
}